// round 4
// baseline (speedup 1.0000x reference)
#include <cuda_runtime.h>
#include <math.h>
#include <stdint.h>

// ---------------- problem constants ----------------
#define N_ROWS 16384
#define D2     1024
#define KSYM   8192
#define BM     128            // rows per CTA (blockIdx.y)
#define BN     128            // symbol cols per CTA (blockIdx.x)
#define BK     32             // k-chunk (floats) per stage = 128B/row
#define NCHUNK (D2 / BK)      // 32
#define RECORDS 128           // per-row top2 records = (KSYM/BN) * 2 warpsN
#define MARGIN 0.5f

// output packing (reference tuple order, flattened, float32)
#define ZQ_OFF   0ULL
#define LOSS_OFF 16777216ULL
#define MIDX_OFF 16777217ULL
#define NCB_OFF  16793601ULL
#define NCS_OFF  25182209ULL
#define NEA_OFF  25190401ULL

// smem stage layout (each segment: 128 rows x 128 bytes, SW128-swizzled)
#define SEG_Z   0
#define SEG_C   16384
#define SEG_CB  32768
#define SEG_GW  49152
#define STAGE   65536
#define NSTAGE  3
#define SMEM_BYTES (NSTAGE * STAGE)

// ---------------- scratch (device globals, no allocation) ----------------
__device__ float  g_cnorm[KSYM];
__device__ float  g_top2v[(size_t)N_ROWS * RECORDS * 2];
__device__ int    g_top2i[(size_t)N_ROWS * RECORDS * 2];
__device__ int    g_midx[N_ROWS];
__device__ int    g_counts[KSYM];
__device__ double g_loss;
__device__ float  g_cs[KSYM];

// ---------------- helpers ----------------
__device__ __forceinline__ uint32_t smem_to_u32(const void* p) {
    uint32_t a;
    asm("{ .reg .u64 t; cvta.to.shared.u64 t, %1; cvt.u32.u64 %0, t; }" : "=r"(a) : "l"(p));
    return a;
}
__device__ __forceinline__ float tanh_approx(float x) {
    float y; asm("tanh.approx.f32 %0, %1;" : "=f"(y) : "f"(x)); return y;
}
__device__ __forceinline__ void cp16(uint32_t dst, const void* src) {
    asm volatile("cp.async.cg.shared.global [%0], [%1], 16;" :: "r"(dst), "l"(src));
}
__device__ __forceinline__ uint32_t lds32(uint32_t addr) {
    uint32_t v; asm volatile("ld.shared.b32 %0, [%1];" : "=r"(v) : "r"(addr)); return v;
}
__device__ __forceinline__ void mma_tf32(float* d, const uint32_t* a, const uint32_t* b) {
    asm volatile(
        "mma.sync.aligned.m16n8k8.row.col.f32.tf32.tf32.f32 "
        "{%0,%1,%2,%3}, {%4,%5,%6,%7}, {%8,%9}, {%0,%1,%2,%3};"
        : "+f"(d[0]), "+f"(d[1]), "+f"(d[2]), "+f"(d[3])
        : "r"(a[0]), "r"(a[1]), "r"(a[2]), "r"(a[3]), "r"(b[0]), "r"(b[1]));
}

// ---------------- 1. codebook row norms (fp64 accumulate) ----------------
__global__ void prep_cnorm_kernel(const float* __restrict__ codebook) {
    int k = blockIdx.x;
    const float* row = codebook + (size_t)k * D2;
    double s = 0.0;
    for (int t = threadIdx.x; t < D2; t += 256) { double v = (double)row[t]; s += v * v; }
    __shared__ double sh[256];
    sh[threadIdx.x] = s; __syncthreads();
    for (int o = 128; o > 0; o >>= 1) { if (threadIdx.x < o) sh[threadIdx.x] += sh[threadIdx.x + o]; __syncthreads(); }
    if (threadIdx.x == 0) g_cnorm[k] = (float)sh[0];
}

// ---------------- 2. init ----------------
__global__ void init_kernel(const float* __restrict__ embed_avg, float* __restrict__ out) {
    size_t total = (size_t)KSYM * D2;
    size_t stride = (size_t)gridDim.x * blockDim.x;
    size_t j = (size_t)blockIdx.x * blockDim.x + threadIdx.x;
    for (size_t i = j; i < total; i += stride) out[NEA_OFF + i] = 0.99f * embed_avg[i];
    if (j < KSYM) g_counts[j] = 0;
    if (j == 0) g_loss = 0.0;
}

// ---------------- 3. fused dual-GEMM score kernel (mma.sync tf32) ----------------
// 256 threads, 8 warps: warp grid 4(M) x 2(N), warp tile 32x64, CTA tile 128x128.
__global__ __launch_bounds__(256, 1)
void score_mma_kernel(const float* __restrict__ z_real,  const float* __restrict__ z_imag,
                      const float* __restrict__ ctx_real, const float* __restrict__ ctx_imag,
                      const int*   __restrict__ prev_idx,
                      const float* __restrict__ codebook, const float* __restrict__ adjacency,
                      const float* __restrict__ gate_w,   const float* __restrict__ gate_b) {
    extern __shared__ char smem[];
    const uint32_t sbu = smem_to_u32(smem);
    const int tid   = threadIdx.x;
    const int wid   = tid >> 5;
    const int lane  = tid & 31;
    const int g     = lane >> 2;      // group id 0..7
    const int tig   = lane & 3;       // thread-in-group
    const int warpM = wid >> 1;       // 0..3 (32 rows each)
    const int warpN = wid & 1;        // 0..1 (64 cols each)
    const int rowBase = blockIdx.y * BM;
    const int cbase   = blockIdx.x * BN;

    // ---- stage loader: 16 x 16B per thread ----
    auto load_stage = [&](int c, int buf) {
        const int k0 = c * BK;
        const float* zs = (k0 < 512) ? z_real : z_imag;
        const float* xs = (k0 < 512) ? ctx_real : ctx_imag;
        const int ko = k0 & 511;
        const uint32_t bb = sbu + (uint32_t)buf * STAGE;
#pragma unroll
        for (int i = 0; i < 4; i++) {
            int q = tid + (i << 8);
            int r = q >> 3, kq = q & 7;
            uint32_t so = (uint32_t)(r * 128 + ((kq * 16) ^ ((r & 7) << 4)));
            size_t gz = (size_t)(rowBase + r) * 512 + ko + kq * 4;
            cp16(bb + SEG_Z + so, zs + gz);
            cp16(bb + SEG_C + so, xs + gz);
            size_t gc = (size_t)(cbase + r) * 1024 + k0 + kq * 4;
            cp16(bb + SEG_CB + so, codebook + gc);
            cp16(bb + SEG_GW + so, gate_w + gc);
        }
        asm volatile("cp.async.commit_group;" ::: "memory");
    };

    float accd[2][8][4], accg[2][8][4];
#pragma unroll
    for (int mt = 0; mt < 2; mt++)
#pragma unroll
        for (int nt = 0; nt < 8; nt++)
#pragma unroll
            for (int e = 0; e < 4; e++) { accd[mt][nt][e] = 0.f; accg[mt][nt][e] = 0.f; }

    const uint32_t swm  = (uint32_t)g << 4;
    const uint32_t aoffZ = SEG_Z  + (uint32_t)(warpM * 32 + g) * 128;
    const uint32_t aoffC = SEG_C  + (uint32_t)(warpM * 32 + g) * 128;
    const uint32_t boffB = SEG_CB + (uint32_t)(warpN * 64 + g) * 128;
    const uint32_t boffW = SEG_GW + (uint32_t)(warpN * 64 + g) * 128;

    // prologue: 2 stages in flight
    load_stage(0, 0);
    load_stage(1, 1);

    int buf = 0;
    for (int c = 0; c < NCHUNK; ++c) {
        if (c + 1 < NCHUNK) asm volatile("cp.async.wait_group 1;" ::: "memory");
        else                asm volatile("cp.async.wait_group 0;" ::: "memory");
        __syncthreads();
        if (c + 2 < NCHUNK) {
            int nb = buf + 2; if (nb >= NSTAGE) nb -= NSTAGE;
            load_stage(c + 2, nb);
        }
        const uint32_t bb = sbu + (uint32_t)buf * STAGE;

#pragma unroll
        for (int ks = 0; ks < 4; ks++) {
            const uint32_t kb0 = ((uint32_t)(ks * 8 + tig) * 4) ^ swm;
            const uint32_t kb1 = kb0 ^ 16u;
            uint32_t az[2][4], ac[2][4];
#pragma unroll
            for (int mt = 0; mt < 2; mt++) {
                uint32_t ro = bb + aoffZ + (uint32_t)mt * 2048;
                az[mt][0] = lds32(ro + kb0);
                az[mt][1] = lds32(ro + 1024 + kb0);
                az[mt][2] = lds32(ro + kb1);
                az[mt][3] = lds32(ro + 1024 + kb1);
                uint32_t rc = bb + aoffC + (uint32_t)mt * 2048;
                ac[mt][0] = lds32(rc + kb0);
                ac[mt][1] = lds32(rc + 1024 + kb0);
                ac[mt][2] = lds32(rc + kb1);
                ac[mt][3] = lds32(rc + 1024 + kb1);
            }
#pragma unroll
            for (int nt = 0; nt < 8; nt++) {
                uint32_t bc[2], bw[2];
                uint32_t ro = bb + boffB + (uint32_t)nt * 1024;
                bc[0] = lds32(ro + kb0);
                bc[1] = lds32(ro + kb1);
                uint32_t rw = bb + boffW + (uint32_t)nt * 1024;
                bw[0] = lds32(rw + kb0);
                bw[1] = lds32(rw + kb1);
#pragma unroll
                for (int mt = 0; mt < 2; mt++) {
                    mma_tf32(accd[mt][nt], az[mt], bc);
                    mma_tf32(accg[mt][nt], ac[mt], bw);
                }
            }
        }
        __syncthreads();
        buf++; if (buf >= NSTAGE) buf = 0;
    }

    // ---- epilogue: bias + per-row top-2 ----
    float cnv[8][2], gbv[8][2];
#pragma unroll
    for (int nt = 0; nt < 8; nt++)
#pragma unroll
        for (int e = 0; e < 2; e++) {
            int col = cbase + warpN * 64 + nt * 8 + 2 * tig + e;
            cnv[nt][e] = g_cnorm[col];
            gbv[nt][e] = gate_b[col];
        }

    const float INF = __int_as_float(0x7f800000);
#pragma unroll
    for (int mt = 0; mt < 2; mt++)
#pragma unroll
        for (int hi = 0; hi < 2; hi++) {
            int rowg = rowBase + warpM * 32 + mt * 16 + hi * 8 + g;
            const float* adjr = adjacency + (size_t)prev_idx[rowg] * KSYM;
            float V1 = INF, V2 = INF;
            int   I1 = 0x7fffffff, I2 = 0x7fffffff;
#pragma unroll
            for (int nt = 0; nt < 8; nt++)
#pragma unroll
                for (int e = 0; e < 2; e++) {
                    int col = cbase + warpN * 64 + nt * 8 + 2 * tig + e;
                    float dot = accd[mt][nt][hi * 2 + e];
                    float gt  = accg[mt][nt][hi * 2 + e];
                    float adj = __ldg(adjr + col);
                    float sig = 1.f / (1.f + __expf(-adj));
                    float th  = tanh_approx(gt + gbv[nt][e]);
                    float s = fmaf(-2.f, dot, cnv[nt][e]) - 0.8f * sig * fmaf(0.5f, th, 1.f);
                    if (s < V1 || (s == V1 && col < I1)) { V2 = V1; I2 = I1; V1 = s; I1 = col; }
                    else if (s < V2 || (s == V2 && col < I2)) { V2 = s; I2 = col; }
                }
            // merge top-2 across the 4 lanes of the row group
#pragma unroll
            for (int off = 1; off <= 2; off <<= 1) {
                float ov1 = __shfl_xor_sync(0xffffffffu, V1, off);
                int   oi1 = __shfl_xor_sync(0xffffffffu, I1, off);
                float ov2 = __shfl_xor_sync(0xffffffffu, V2, off);
                int   oi2 = __shfl_xor_sync(0xffffffffu, I2, off);
                if (ov1 < V1 || (ov1 == V1 && oi1 < I1)) {
                    float nv2; int ni2;
                    if (V1 < ov2 || (V1 == ov2 && I1 < oi2)) { nv2 = V1; ni2 = I1; }
                    else { nv2 = ov2; ni2 = oi2; }
                    V1 = ov1; I1 = oi1; V2 = nv2; I2 = ni2;
                } else if (ov1 < V2 || (ov1 == V2 && oi1 < I2)) {
                    V2 = ov1; I2 = oi1;
                }
            }
            if (tig == 0) {
                size_t o = ((size_t)rowg * RECORDS + blockIdx.x * 2 + warpN) * 2;
                g_top2v[o] = V1;  g_top2i[o] = I1;
                g_top2v[o + 1] = V2; g_top2i[o + 1] = I2;
            }
        }
}

// ---------------- 4. merge top-2s; fp64 refinement for near-ties ----------------
__global__ void merge_refine_kernel(const float* __restrict__ z_real,  const float* __restrict__ z_imag,
                                    const float* __restrict__ ctx_real, const float* __restrict__ ctx_imag,
                                    const int*   __restrict__ prev_idx,
                                    const float* __restrict__ codebook, const float* __restrict__ adjacency,
                                    const float* __restrict__ gate_w,   const float* __restrict__ gate_b,
                                    float* __restrict__ out) {
    int gwarp = (blockIdx.x * blockDim.x + threadIdx.x) >> 5;
    int lane = threadIdx.x & 31;
    if (gwarp >= N_ROWS) return;
    const int n = gwarp;
    const float INF = __int_as_float(0x7f800000);

    float v1 = INF, v2 = INF;
    int i1 = 0x7fffffff, i2 = 0x7fffffff;
    const size_t base = (size_t)n * (RECORDS * 2);
#pragma unroll
    for (int q = 0; q < 8; q++) {
        int e = lane + q * 32;
        float v = g_top2v[base + e];
        int ix  = g_top2i[base + e];
        if (v < v1 || (v == v1 && ix < i1)) { v2 = v1; i2 = i1; v1 = v; i1 = ix; }
        else if (v < v2 || (v == v2 && ix < i2)) { v2 = v; i2 = ix; }
    }
#pragma unroll
    for (int off = 16; off; off >>= 1) {
        float ov1 = __shfl_down_sync(0xffffffffu, v1, off);
        float ov2 = __shfl_down_sync(0xffffffffu, v2, off);
        int   oi1 = __shfl_down_sync(0xffffffffu, i1, off);
        int   oi2 = __shfl_down_sync(0xffffffffu, i2, off);
        if (ov1 < v1 || (ov1 == v1 && oi1 < i1)) { v2 = v1; i2 = i1; v1 = ov1; i1 = oi1; }
        else if (ov1 < v2 || (ov1 == v2 && oi1 < i2)) { v2 = ov1; i2 = oi1; }
        if (ov2 < v1 || (ov2 == v1 && oi2 < i1)) { v2 = v1; i2 = i1; v1 = ov2; i1 = oi2; }
        else if (ov2 < v2 || (ov2 == v2 && oi2 < i2)) { v2 = ov2; i2 = oi2; }
    }
    float bv1 = __shfl_sync(0xffffffffu, v1, 0);
    float bv2 = __shfl_sync(0xffffffffu, v2, 0);
    int   bi1 = __shfl_sync(0xffffffffu, i1, 0);
    int   bi2 = __shfl_sync(0xffffffffu, i2, 0);

    int pick = bi1;
    if (bv2 - bv1 < MARGIN) {
        double a0 = 0, a1 = 0, a2 = 0, a3 = 0, a4 = 0, a5 = 0;
        for (int t = lane; t < D2; t += 32) {
            double zt = (t < 512) ? (double)z_real[(size_t)n * 512 + t]
                                  : (double)z_imag[(size_t)n * 512 + t - 512];
            double xt = (t < 512) ? (double)ctx_real[(size_t)n * 512 + t]
                                  : (double)ctx_imag[(size_t)n * 512 + t - 512];
            double c1 = (double)codebook[(size_t)bi1 * D2 + t];
            double w1 = (double)gate_w[(size_t)bi1 * D2 + t];
            double c2 = (double)codebook[(size_t)bi2 * D2 + t];
            double w2 = (double)gate_w[(size_t)bi2 * D2 + t];
            a0 += c1 * c1; a1 += zt * c1; a2 += xt * w1;
            a3 += c2 * c2; a4 += zt * c2; a5 += xt * w2;
        }
        for (int o = 16; o; o >>= 1) {
            a0 += __shfl_down_sync(0xffffffffu, a0, o);
            a1 += __shfl_down_sync(0xffffffffu, a1, o);
            a2 += __shfl_down_sync(0xffffffffu, a2, o);
            a3 += __shfl_down_sync(0xffffffffu, a3, o);
            a4 += __shfl_down_sync(0xffffffffu, a4, o);
            a5 += __shfl_down_sync(0xffffffffu, a5, o);
        }
        if (lane == 0) {
            int p = prev_idx[n];
            double ad1 = (double)adjacency[(size_t)p * KSYM + bi1];
            double ad2 = (double)adjacency[(size_t)p * KSYM + bi2];
            double gb1 = (double)gate_b[bi1];
            double gb2 = (double)gate_b[bi2];
            double d1 = a0 - 2.0 * a1 - 0.8 * (1.0 / (1.0 + exp(-ad1))) * (1.0 + 0.5 * tanh(a2 + gb1));
            double d2 = a3 - 2.0 * a4 - 0.8 * (1.0 / (1.0 + exp(-ad2))) * (1.0 + 0.5 * tanh(a5 + gb2));
            pick = (d2 < d1 || (d2 == d1 && bi2 < bi1)) ? bi2 : bi1;
        }
        pick = __shfl_sync(0xffffffffu, pick, 0);
    }
    if (lane == 0) {
        g_midx[n] = pick;
        out[MIDX_OFF + n] = (float)pick;
        atomicAdd(&g_counts[pick], 1);
    }
}

// ---------------- 5. z_q gather, embed_sum scatter, loss ----------------
__global__ void scatter_kernel(const float* __restrict__ z_real, const float* __restrict__ z_imag,
                               const float* __restrict__ codebook, float* __restrict__ out) {
    const int n = blockIdx.x;
    const int m = g_midx[n];
    const int tid = threadIdx.x;
    const int d0 = tid * 4;

    float4 c = *(const float4*)(codebook + (size_t)m * D2 + d0);
    float4 z;
    if (d0 < 512) z = *(const float4*)(z_real + (size_t)n * 512 + d0);
    else          z = *(const float4*)(z_imag + (size_t)n * 512 + d0 - 512);

    *(float4*)(out + ZQ_OFF + (size_t)n * D2 + d0) = c;

    float* ea = out + NEA_OFF + (size_t)m * D2 + d0;
    atomicAdd(ea + 0, 0.01f * z.x);
    atomicAdd(ea + 1, 0.01f * z.y);
    atomicAdd(ea + 2, 0.01f * z.z);
    atomicAdd(ea + 3, 0.01f * z.w);

    float dx = c.x - z.x, dy = c.y - z.y, dz = c.z - z.z, dw = c.w - z.w;
    float lsum = dx * dx + dy * dy + dz * dz + dw * dw;

    __shared__ float sh[256];
    sh[tid] = lsum; __syncthreads();
    for (int o = 128; o > 0; o >>= 1) { if (tid < o) sh[tid] += sh[tid + o]; __syncthreads(); }
    if (tid == 0) atomicAdd(&g_loss, (double)sh[0]);
}

// ---------------- 6a. cluster-size EMA, cs, loss ----------------
__global__ void finalize_a_kernel(const float* __restrict__ cluster_size, float* __restrict__ out) {
    const int tid = threadIdx.x;  // 1024 threads
    float ncs[8];
    float psum = 0.f;
#pragma unroll
    for (int q = 0; q < 8; q++) {
        int k = tid * 8 + q;
        float v = cluster_size[k] * 0.99f + 0.01f * (float)g_counts[k];
        ncs[q] = v;
        out[NCS_OFF + k] = v;
        psum += v;
    }
    __shared__ float sh[1024];
    sh[tid] = psum; __syncthreads();
    for (int o = 512; o > 0; o >>= 1) { if (tid < o) sh[tid] += sh[tid + o]; __syncthreads(); }
    float ntot = sh[0];
#pragma unroll
    for (int q = 0; q < 8; q++) {
        float cs = (ncs[q] + 1e-6f) / (ntot + (float)KSYM * 1e-6f) * ntot;
        g_cs[tid * 8 + q] = cs;
    }
    if (tid == 0) out[LOSS_OFF] = (float)(1.25 * g_loss / 16777216.0);
}

// ---------------- 6b. new_codebook = new_embed_avg / cs ----------------
__global__ void finalize_b_kernel(float* __restrict__ out) {
    size_t total = (size_t)KSYM * D2;
    size_t stride = (size_t)gridDim.x * blockDim.x;
    for (size_t i = (size_t)blockIdx.x * blockDim.x + threadIdx.x; i < total; i += stride) {
        int k = (int)(i >> 10);
        out[NCB_OFF + i] = out[NEA_OFF + i] / g_cs[k];
    }
}

// ---------------- entry ----------------
extern "C" void kernel_launch(void* const* d_in, const int* in_sizes, int n_in,
                              void* d_out, int out_size) {
    const float* z_real     = (const float*)d_in[0];
    const float* z_imag     = (const float*)d_in[1];
    const float* ctx_real   = (const float*)d_in[2];
    const float* ctx_imag   = (const float*)d_in[3];
    const int*   prev_idx   = (const int*)d_in[4];
    const float* codebook   = (const float*)d_in[5];
    const float* adjacency  = (const float*)d_in[6];
    const float* gate_w     = (const float*)d_in[7];
    const float* gate_b     = (const float*)d_in[8];
    const float* cluster_sz = (const float*)d_in[9];
    const float* embed_avg  = (const float*)d_in[10];
    float* out = (float*)d_out;

    cudaFuncSetAttribute(score_mma_kernel, cudaFuncAttributeMaxDynamicSharedMemorySize, SMEM_BYTES);

    prep_cnorm_kernel<<<KSYM, 256>>>(codebook);
    init_kernel<<<8192, 256>>>(embed_avg, out);
    // blockIdx.x = column tile (fast) so codebook/gate_w stay L2-resident
    score_mma_kernel<<<dim3(KSYM / BN, N_ROWS / BM), 256, SMEM_BYTES>>>(
        z_real, z_imag, ctx_real, ctx_imag, prev_idx, codebook, adjacency, gate_w, gate_b);
    merge_refine_kernel<<<N_ROWS / 8, 256>>>(z_real, z_imag, ctx_real, ctx_imag,
                                             prev_idx, codebook, adjacency, gate_w, gate_b, out);
    scatter_kernel<<<N_ROWS, 256>>>(z_real, z_imag, codebook, out);
    finalize_a_kernel<<<1, 1024>>>(cluster_sz, out);
    finalize_b_kernel<<<8192, 256>>>(out);
}

// round 5
// speedup vs baseline: 1.1814x; 1.1814x over previous
#include <cuda_runtime.h>
#include <cuda_bf16.h>
#include <math.h>
#include <stdint.h>

// ---------------- problem constants ----------------
#define N_ROWS 16384
#define D2     1024
#define KSYM   8192
#define BM     128            // rows per CTA (blockIdx.y)
#define BN     128            // symbol cols per CTA (blockIdx.x)
#define BK     32             // k-chunk per stage
#define NCHUNK (D2 / BK)      // 32
#define RECORDS 256           // per-row top2 records = (KSYM/BN)=64 col tiles * 4 warpN
#define MARGIN 0.5f

// output packing (reference tuple order, flattened, float32)
#define ZQ_OFF   0ULL
#define LOSS_OFF 16777216ULL
#define MIDX_OFF 16777217ULL
#define NCB_OFF  16793601ULL
#define NCS_OFF  25182209ULL
#define NEA_OFF  25190401ULL

// smem stage layout:
//  z   : 128 rows x 128B  (fp32, XOR swizzle)      @ 0      (16384B)
//  ctx : 128 rows x 80B   (bf16, 64B data + pad)   @ 16384  (10240B)
//  cb  : 128 rows x 128B  (fp32, XOR swizzle)      @ 26624  (16384B)
//  gw  : 128 rows x 80B   (bf16)                   @ 43008  (10240B)
#define SEG_Z   0
#define SEG_C   16384
#define SEG_CB  26624
#define SEG_GW  43008
#define STAGE   53248
#define NSTAGE  3
#define SMEM_BYTES (NSTAGE * STAGE)   // 159744

// ---------------- scratch (device globals, no allocation) ----------------
__device__ float  g_cnorm[KSYM];
__device__ float  g_top2v[(size_t)N_ROWS * RECORDS * 2];
__device__ int    g_top2i[(size_t)N_ROWS * RECORDS * 2];
__device__ int    g_midx[N_ROWS];
__device__ int    g_counts[KSYM];
__device__ double g_loss;
__device__ float  g_cs[KSYM];
__device__ __nv_bfloat16 g_ctxb[(size_t)N_ROWS * D2];   // 32MB bf16 ctx (concat)
__device__ __nv_bfloat16 g_gwb[(size_t)KSYM * D2];      // 16MB bf16 gate_w

// ---------------- helpers ----------------
__device__ __forceinline__ uint32_t smem_to_u32(const void* p) {
    uint32_t a;
    asm("{ .reg .u64 t; cvta.to.shared.u64 t, %1; cvt.u32.u64 %0, t; }" : "=r"(a) : "l"(p));
    return a;
}
__device__ __forceinline__ float tanh_approx(float x) {
    float y; asm("tanh.approx.f32 %0, %1;" : "=f"(y) : "f"(x)); return y;
}
__device__ __forceinline__ void cp16(uint32_t dst, const void* src) {
    asm volatile("cp.async.cg.shared.global [%0], [%1], 16;" :: "r"(dst), "l"(src));
}
__device__ __forceinline__ uint32_t lds32(uint32_t addr) {
    uint32_t v; asm volatile("ld.shared.b32 %0, [%1];" : "=r"(v) : "r"(addr)); return v;
}
__device__ __forceinline__ void mma_tf32(float* d, const uint32_t* a, const uint32_t* b) {
    asm volatile(
        "mma.sync.aligned.m16n8k8.row.col.f32.tf32.tf32.f32 "
        "{%0,%1,%2,%3}, {%4,%5,%6,%7}, {%8,%9}, {%0,%1,%2,%3};"
        : "+f"(d[0]), "+f"(d[1]), "+f"(d[2]), "+f"(d[3])
        : "r"(a[0]), "r"(a[1]), "r"(a[2]), "r"(a[3]), "r"(b[0]), "r"(b[1]));
}
__device__ __forceinline__ void mma_bf16(float* d, const uint32_t* a, const uint32_t* b) {
    asm volatile(
        "mma.sync.aligned.m16n8k16.row.col.f32.bf16.bf16.f32 "
        "{%0,%1,%2,%3}, {%4,%5,%6,%7}, {%8,%9}, {%0,%1,%2,%3};"
        : "+f"(d[0]), "+f"(d[1]), "+f"(d[2]), "+f"(d[3])
        : "r"(a[0]), "r"(a[1]), "r"(a[2]), "r"(a[3]), "r"(b[0]), "r"(b[1]));
}

// ---------------- 0. bf16 conversion prep ----------------
__global__ void conv_ctx_kernel(const float* __restrict__ cr, const float* __restrict__ ci) {
    size_t total = (size_t)N_ROWS * D2;
    size_t stride = (size_t)gridDim.x * blockDim.x;
    for (size_t i = (size_t)blockIdx.x * blockDim.x + threadIdx.x; i < total; i += stride) {
        int n = (int)(i >> 10), d = (int)(i & 1023);
        float v = (d < 512) ? cr[(size_t)n * 512 + d] : ci[(size_t)n * 512 + d - 512];
        g_ctxb[i] = __float2bfloat16(v);
    }
}
__global__ void conv_gw_kernel(const float* __restrict__ gw) {
    size_t total = (size_t)KSYM * D2;
    size_t stride = (size_t)gridDim.x * blockDim.x;
    for (size_t i = (size_t)blockIdx.x * blockDim.x + threadIdx.x; i < total; i += stride)
        g_gwb[i] = __float2bfloat16(gw[i]);
}

// ---------------- 1. codebook row norms (fp64 accumulate) ----------------
__global__ void prep_cnorm_kernel(const float* __restrict__ codebook) {
    int k = blockIdx.x;
    const float* row = codebook + (size_t)k * D2;
    double s = 0.0;
    for (int t = threadIdx.x; t < D2; t += 256) { double v = (double)row[t]; s += v * v; }
    __shared__ double sh[256];
    sh[threadIdx.x] = s; __syncthreads();
    for (int o = 128; o > 0; o >>= 1) { if (threadIdx.x < o) sh[threadIdx.x] += sh[threadIdx.x + o]; __syncthreads(); }
    if (threadIdx.x == 0) g_cnorm[k] = (float)sh[0];
}

// ---------------- 2. init ----------------
__global__ void init_kernel(const float* __restrict__ embed_avg, float* __restrict__ out) {
    size_t total = (size_t)KSYM * D2;
    size_t stride = (size_t)gridDim.x * blockDim.x;
    size_t j = (size_t)blockIdx.x * blockDim.x + threadIdx.x;
    for (size_t i = j; i < total; i += stride) out[NEA_OFF + i] = 0.99f * embed_avg[i];
    if (j < KSYM) g_counts[j] = 0;
    if (j == 0) g_loss = 0.0;
}

// ---------------- 3. fused dual-GEMM score kernel ----------------
// 512 threads, 16 warps: warp grid 4(M) x 4(N), warp tile 32x32, CTA tile 128x128.
// dot gemm: tf32 m16n8k8 from fp32 smem; gate gemm: bf16 m16n8k16 from bf16 smem.
__global__ __launch_bounds__(512, 1)
void score_mma_kernel(const float* __restrict__ z_real,  const float* __restrict__ z_imag,
                      const int*   __restrict__ prev_idx,
                      const float* __restrict__ codebook, const float* __restrict__ adjacency,
                      const float* __restrict__ gate_b) {
    extern __shared__ char smem[];
    const uint32_t sbu = smem_to_u32(smem);
    const int tid   = threadIdx.x;
    const int wid   = tid >> 5;
    const int lane  = tid & 31;
    const int g     = lane >> 2;      // group id 0..7
    const int tig   = lane & 3;       // thread-in-group
    const int warpM = wid >> 2;       // 0..3 (32 rows each)
    const int warpN = wid & 3;        // 0..3 (32 cols each)
    const int rowBase = blockIdx.y * BM;
    const int cbase   = blockIdx.x * BN;

    const char* ctxb = (const char*)g_ctxb;
    const char* gwb  = (const char*)g_gwb;

    // ---- stage loader: 6 x 16B per thread ----
    auto load_stage = [&](int c, int buf) {
        const int k0 = c * BK;
        const float* zs = (k0 < 512) ? z_real : z_imag;
        const int ko = k0 & 511;
        const uint32_t bb = sbu + (uint32_t)buf * STAGE;
        // z + cb: 1024 quads each, swizzled 128B rows
#pragma unroll
        for (int i = 0; i < 2; i++) {
            int q = tid + (i << 9);
            int r = q >> 3, q8 = q & 7;
            uint32_t so = (uint32_t)(r * 128 + ((q8 * 16) ^ ((r & 7) << 4)));
            cp16(bb + SEG_Z + so, zs + (size_t)(rowBase + r) * 512 + ko + q8 * 4);
            cp16(bb + SEG_CB + so, codebook + (size_t)(cbase + r) * 1024 + k0 + q8 * 4);
        }
        // ctx + gw bf16: 512 quads each, 80B-padded rows (64B data)
        {
            int r = tid >> 2, qq = tid & 3;
            uint32_t so = (uint32_t)(r * 80 + qq * 16);
            cp16(bb + SEG_C + so, ctxb + (size_t)(rowBase + r) * 2048 + (size_t)k0 * 2 + qq * 16);
            cp16(bb + SEG_GW + so, gwb + (size_t)(cbase + r) * 2048 + (size_t)k0 * 2 + qq * 16);
        }
        asm volatile("cp.async.commit_group;" ::: "memory");
    };

    float accd[2][4][4], accg[2][4][4];
#pragma unroll
    for (int mt = 0; mt < 2; mt++)
#pragma unroll
        for (int nt = 0; nt < 4; nt++)
#pragma unroll
            for (int e = 0; e < 4; e++) { accd[mt][nt][e] = 0.f; accg[mt][nt][e] = 0.f; }

    const uint32_t swm  = (uint32_t)g << 4;
    const uint32_t aoffZ = SEG_Z  + (uint32_t)(warpM * 32 + g) * 128;       // fp32 z rows
    const uint32_t boffB = SEG_CB + (uint32_t)(warpN * 32 + g) * 128;       // fp32 cb rows
    const uint32_t aoffC = SEG_C  + (uint32_t)(warpM * 32 + g) * 80 + tig * 4;  // bf16 ctx
    const uint32_t boffW = SEG_GW + (uint32_t)(warpN * 32 + g) * 80 + tig * 4;  // bf16 gw

    // prologue: 2 stages in flight
    load_stage(0, 0);
    load_stage(1, 1);

    int buf = 0;
    for (int c = 0; c < NCHUNK; ++c) {
        if (c + 1 < NCHUNK) asm volatile("cp.async.wait_group 1;" ::: "memory");
        else                asm volatile("cp.async.wait_group 0;" ::: "memory");
        __syncthreads();
        if (c + 2 < NCHUNK) {
            int nb = buf + 2; if (nb >= NSTAGE) nb -= NSTAGE;
            load_stage(c + 2, nb);
        }
        const uint32_t bb = sbu + (uint32_t)buf * STAGE;

        // ---- dot gemm: 4 x k8 tf32 steps ----
#pragma unroll
        for (int ks = 0; ks < 4; ks++) {
            const uint32_t kb0 = ((uint32_t)(ks * 8 + tig) * 4) ^ swm;
            const uint32_t kb1 = kb0 ^ 16u;
            uint32_t az[2][4];
#pragma unroll
            for (int mt = 0; mt < 2; mt++) {
                uint32_t ro = bb + aoffZ + (uint32_t)mt * 2048;
                az[mt][0] = lds32(ro + kb0);
                az[mt][1] = lds32(ro + 1024 + kb0);
                az[mt][2] = lds32(ro + kb1);
                az[mt][3] = lds32(ro + 1024 + kb1);
            }
#pragma unroll
            for (int nt = 0; nt < 4; nt++) {
                uint32_t bc[2];
                uint32_t ro = bb + boffB + (uint32_t)nt * 1024;
                bc[0] = lds32(ro + kb0);
                bc[1] = lds32(ro + kb1);
#pragma unroll
                for (int mt = 0; mt < 2; mt++) mma_tf32(accd[mt][nt], az[mt], bc);
            }
        }
        // ---- gate gemm: 2 x k16 bf16 steps ----
#pragma unroll
        for (int ks = 0; ks < 2; ks++) {
            const uint32_t kb = (uint32_t)(ks * 32);
            uint32_t ag[2][4];
#pragma unroll
            for (int mt = 0; mt < 2; mt++) {
                uint32_t ro = bb + aoffC + (uint32_t)mt * 1280 + kb;   // 16 rows * 80B
                ag[mt][0] = lds32(ro);
                ag[mt][1] = lds32(ro + 640);                            // +8 rows
                ag[mt][2] = lds32(ro + 16);
                ag[mt][3] = lds32(ro + 640 + 16);
            }
#pragma unroll
            for (int nt = 0; nt < 4; nt++) {
                uint32_t bw[2];
                uint32_t ro = bb + boffW + (uint32_t)nt * 640 + kb;
                bw[0] = lds32(ro);
                bw[1] = lds32(ro + 16);
#pragma unroll
                for (int mt = 0; mt < 2; mt++) mma_bf16(accg[mt][nt], ag[mt], bw);
            }
        }
        __syncthreads();
        buf++; if (buf >= NSTAGE) buf = 0;
    }

    // ---- epilogue: bias + per-row top-2 ----
    float cnv[4][2], gbv[4][2];
#pragma unroll
    for (int nt = 0; nt < 4; nt++)
#pragma unroll
        for (int e = 0; e < 2; e++) {
            int col = cbase + warpN * 32 + nt * 8 + 2 * tig + e;
            cnv[nt][e] = g_cnorm[col];
            gbv[nt][e] = gate_b[col];
        }

    const float INF = __int_as_float(0x7f800000);
#pragma unroll
    for (int mt = 0; mt < 2; mt++)
#pragma unroll
        for (int hi = 0; hi < 2; hi++) {
            int rowg = rowBase + warpM * 32 + mt * 16 + hi * 8 + g;
            const float* adjr = adjacency + (size_t)prev_idx[rowg] * KSYM;
            float V1 = INF, V2 = INF;
            int   I1 = 0x7fffffff, I2 = 0x7fffffff;
#pragma unroll
            for (int nt = 0; nt < 4; nt++)
#pragma unroll
                for (int e = 0; e < 2; e++) {
                    int col = cbase + warpN * 32 + nt * 8 + 2 * tig + e;
                    float dot = accd[mt][nt][hi * 2 + e];
                    float gt  = accg[mt][nt][hi * 2 + e];
                    float adj = __ldg(adjr + col);
                    float sig = 1.f / (1.f + __expf(-adj));
                    float th  = tanh_approx(gt + gbv[nt][e]);
                    float s = fmaf(-2.f, dot, cnv[nt][e]) - 0.8f * sig * fmaf(0.5f, th, 1.f);
                    if (s < V1 || (s == V1 && col < I1)) { V2 = V1; I2 = I1; V1 = s; I1 = col; }
                    else if (s < V2 || (s == V2 && col < I2)) { V2 = s; I2 = col; }
                }
            // merge top-2 across the 4 lanes of the row group
#pragma unroll
            for (int off = 1; off <= 2; off <<= 1) {
                float ov1 = __shfl_xor_sync(0xffffffffu, V1, off);
                int   oi1 = __shfl_xor_sync(0xffffffffu, I1, off);
                float ov2 = __shfl_xor_sync(0xffffffffu, V2, off);
                int   oi2 = __shfl_xor_sync(0xffffffffu, I2, off);
                if (ov1 < V1 || (ov1 == V1 && oi1 < I1)) {
                    float nv2; int ni2;
                    if (V1 < ov2 || (V1 == ov2 && I1 < oi2)) { nv2 = V1; ni2 = I1; }
                    else { nv2 = ov2; ni2 = oi2; }
                    V1 = ov1; I1 = oi1; V2 = nv2; I2 = ni2;
                } else if (ov1 < V2 || (ov1 == V2 && oi1 < I2)) {
                    V2 = ov1; I2 = oi1;
                }
            }
            if (tig == 0) {
                size_t o = ((size_t)rowg * RECORDS + blockIdx.x * 4 + warpN) * 2;
                g_top2v[o] = V1;  g_top2i[o] = I1;
                g_top2v[o + 1] = V2; g_top2i[o + 1] = I2;
            }
        }
}

// ---------------- 4. merge top-2s; fp64 refinement for near-ties ----------------
__global__ void merge_refine_kernel(const float* __restrict__ z_real,  const float* __restrict__ z_imag,
                                    const float* __restrict__ ctx_real, const float* __restrict__ ctx_imag,
                                    const int*   __restrict__ prev_idx,
                                    const float* __restrict__ codebook, const float* __restrict__ adjacency,
                                    const float* __restrict__ gate_w,   const float* __restrict__ gate_b,
                                    float* __restrict__ out) {
    int gwarp = (blockIdx.x * blockDim.x + threadIdx.x) >> 5;
    int lane = threadIdx.x & 31;
    if (gwarp >= N_ROWS) return;
    const int n = gwarp;
    const float INF = __int_as_float(0x7f800000);

    float v1 = INF, v2 = INF;
    int i1 = 0x7fffffff, i2 = 0x7fffffff;
    const size_t base = (size_t)n * (RECORDS * 2);
#pragma unroll
    for (int q = 0; q < 16; q++) {
        int e = lane + q * 32;
        float v = g_top2v[base + e];
        int ix  = g_top2i[base + e];
        if (v < v1 || (v == v1 && ix < i1)) { v2 = v1; i2 = i1; v1 = v; i1 = ix; }
        else if (v < v2 || (v == v2 && ix < i2)) { v2 = v; i2 = ix; }
    }
#pragma unroll
    for (int off = 16; off; off >>= 1) {
        float ov1 = __shfl_down_sync(0xffffffffu, v1, off);
        float ov2 = __shfl_down_sync(0xffffffffu, v2, off);
        int   oi1 = __shfl_down_sync(0xffffffffu, i1, off);
        int   oi2 = __shfl_down_sync(0xffffffffu, i2, off);
        if (ov1 < v1 || (ov1 == v1 && oi1 < i1)) { v2 = v1; i2 = i1; v1 = ov1; i1 = oi1; }
        else if (ov1 < v2 || (ov1 == v2 && oi1 < i2)) { v2 = ov1; i2 = oi1; }
        if (ov2 < v1 || (ov2 == v1 && oi2 < i1)) { v2 = v1; i2 = i1; v1 = ov2; i1 = oi2; }
        else if (ov2 < v2 || (ov2 == v2 && oi2 < i2)) { v2 = ov2; i2 = oi2; }
    }
    float bv1 = __shfl_sync(0xffffffffu, v1, 0);
    float bv2 = __shfl_sync(0xffffffffu, v2, 0);
    int   bi1 = __shfl_sync(0xffffffffu, i1, 0);
    int   bi2 = __shfl_sync(0xffffffffu, i2, 0);

    int pick = bi1;
    if (bv2 - bv1 < MARGIN) {
        double a0 = 0, a1 = 0, a2 = 0, a3 = 0, a4 = 0, a5 = 0;
        for (int t = lane; t < D2; t += 32) {
            double zt = (t < 512) ? (double)z_real[(size_t)n * 512 + t]
                                  : (double)z_imag[(size_t)n * 512 + t - 512];
            double xt = (t < 512) ? (double)ctx_real[(size_t)n * 512 + t]
                                  : (double)ctx_imag[(size_t)n * 512 + t - 512];
            double c1 = (double)codebook[(size_t)bi1 * D2 + t];
            double w1 = (double)gate_w[(size_t)bi1 * D2 + t];
            double c2 = (double)codebook[(size_t)bi2 * D2 + t];
            double w2 = (double)gate_w[(size_t)bi2 * D2 + t];
            a0 += c1 * c1; a1 += zt * c1; a2 += xt * w1;
            a3 += c2 * c2; a4 += zt * c2; a5 += xt * w2;
        }
        for (int o = 16; o; o >>= 1) {
            a0 += __shfl_down_sync(0xffffffffu, a0, o);
            a1 += __shfl_down_sync(0xffffffffu, a1, o);
            a2 += __shfl_down_sync(0xffffffffu, a2, o);
            a3 += __shfl_down_sync(0xffffffffu, a3, o);
            a4 += __shfl_down_sync(0xffffffffu, a4, o);
            a5 += __shfl_down_sync(0xffffffffu, a5, o);
        }
        if (lane == 0) {
            int p = prev_idx[n];
            double ad1 = (double)adjacency[(size_t)p * KSYM + bi1];
            double ad2 = (double)adjacency[(size_t)p * KSYM + bi2];
            double gb1 = (double)gate_b[bi1];
            double gb2 = (double)gate_b[bi2];
            double d1 = a0 - 2.0 * a1 - 0.8 * (1.0 / (1.0 + exp(-ad1))) * (1.0 + 0.5 * tanh(a2 + gb1));
            double d2 = a3 - 2.0 * a4 - 0.8 * (1.0 / (1.0 + exp(-ad2))) * (1.0 + 0.5 * tanh(a5 + gb2));
            pick = (d2 < d1 || (d2 == d1 && bi2 < bi1)) ? bi2 : bi1;
        }
        pick = __shfl_sync(0xffffffffu, pick, 0);
    }
    if (lane == 0) {
        g_midx[n] = pick;
        out[MIDX_OFF + n] = (float)pick;
        atomicAdd(&g_counts[pick], 1);
    }
}

// ---------------- 5. z_q gather, embed_sum scatter, loss ----------------
__global__ void scatter_kernel(const float* __restrict__ z_real, const float* __restrict__ z_imag,
                               const float* __restrict__ codebook, float* __restrict__ out) {
    const int n = blockIdx.x;
    const int m = g_midx[n];
    const int tid = threadIdx.x;
    const int d0 = tid * 4;

    float4 c = *(const float4*)(codebook + (size_t)m * D2 + d0);
    float4 z;
    if (d0 < 512) z = *(const float4*)(z_real + (size_t)n * 512 + d0);
    else          z = *(const float4*)(z_imag + (size_t)n * 512 + d0 - 512);

    *(float4*)(out + ZQ_OFF + (size_t)n * D2 + d0) = c;

    float* ea = out + NEA_OFF + (size_t)m * D2 + d0;
    atomicAdd(ea + 0, 0.01f * z.x);
    atomicAdd(ea + 1, 0.01f * z.y);
    atomicAdd(ea + 2, 0.01f * z.z);
    atomicAdd(ea + 3, 0.01f * z.w);

    float dx = c.x - z.x, dy = c.y - z.y, dz = c.z - z.z, dw = c.w - z.w;
    float lsum = dx * dx + dy * dy + dz * dz + dw * dw;

    __shared__ float sh[256];
    sh[tid] = lsum; __syncthreads();
    for (int o = 128; o > 0; o >>= 1) { if (tid < o) sh[tid] += sh[tid + o]; __syncthreads(); }
    if (tid == 0) atomicAdd(&g_loss, (double)sh[0]);
}

// ---------------- 6a. cluster-size EMA, cs, loss ----------------
__global__ void finalize_a_kernel(const float* __restrict__ cluster_size, float* __restrict__ out) {
    const int tid = threadIdx.x;  // 1024 threads
    float ncs[8];
    float psum = 0.f;
#pragma unroll
    for (int q = 0; q < 8; q++) {
        int k = tid * 8 + q;
        float v = cluster_size[k] * 0.99f + 0.01f * (float)g_counts[k];
        ncs[q] = v;
        out[NCS_OFF + k] = v;
        psum += v;
    }
    __shared__ float sh[1024];
    sh[tid] = psum; __syncthreads();
    for (int o = 512; o > 0; o >>= 1) { if (tid < o) sh[tid] += sh[tid + o]; __syncthreads(); }
    float ntot = sh[0];
#pragma unroll
    for (int q = 0; q < 8; q++) {
        float cs = (ncs[q] + 1e-6f) / (ntot + (float)KSYM * 1e-6f) * ntot;
        g_cs[tid * 8 + q] = cs;
    }
    if (tid == 0) out[LOSS_OFF] = (float)(1.25 * g_loss / 16777216.0);
}

// ---------------- 6b. new_codebook = new_embed_avg / cs ----------------
__global__ void finalize_b_kernel(float* __restrict__ out) {
    size_t total = (size_t)KSYM * D2;
    size_t stride = (size_t)gridDim.x * blockDim.x;
    for (size_t i = (size_t)blockIdx.x * blockDim.x + threadIdx.x; i < total; i += stride) {
        int k = (int)(i >> 10);
        out[NCB_OFF + i] = out[NEA_OFF + i] / g_cs[k];
    }
}

// ---------------- entry ----------------
extern "C" void kernel_launch(void* const* d_in, const int* in_sizes, int n_in,
                              void* d_out, int out_size) {
    const float* z_real     = (const float*)d_in[0];
    const float* z_imag     = (const float*)d_in[1];
    const float* ctx_real   = (const float*)d_in[2];
    const float* ctx_imag   = (const float*)d_in[3];
    const int*   prev_idx   = (const int*)d_in[4];
    const float* codebook   = (const float*)d_in[5];
    const float* adjacency  = (const float*)d_in[6];
    const float* gate_w     = (const float*)d_in[7];
    const float* gate_b     = (const float*)d_in[8];
    const float* cluster_sz = (const float*)d_in[9];
    const float* embed_avg  = (const float*)d_in[10];
    float* out = (float*)d_out;

    cudaFuncSetAttribute(score_mma_kernel, cudaFuncAttributeMaxDynamicSharedMemorySize, SMEM_BYTES);

    conv_ctx_kernel<<<4096, 256>>>(ctx_real, ctx_imag);
    conv_gw_kernel<<<4096, 256>>>(gate_w);
    prep_cnorm_kernel<<<KSYM, 256>>>(codebook);
    init_kernel<<<8192, 256>>>(embed_avg, out);
    // blockIdx.x = column tile (fast) so codebook/gate_w stay L2-resident
    score_mma_kernel<<<dim3(KSYM / BN, N_ROWS / BM), 512, SMEM_BYTES>>>(
        z_real, z_imag, prev_idx, codebook, adjacency, gate_b);
    merge_refine_kernel<<<N_ROWS / 8, 256>>>(z_real, z_imag, ctx_real, ctx_imag,
                                             prev_idx, codebook, adjacency, gate_w, gate_b, out);
    scatter_kernel<<<N_ROWS, 256>>>(z_real, z_imag, codebook, out);
    finalize_a_kernel<<<1, 1024>>>(cluster_sz, out);
    finalize_b_kernel<<<8192, 256>>>(out);
}

// round 6
// speedup vs baseline: 1.1936x; 1.0103x over previous
#include <cuda_runtime.h>
#include <cuda_bf16.h>
#include <math.h>
#include <stdint.h>

// ---------------- problem constants ----------------
#define N_ROWS 16384
#define D2     1024
#define KSYM   8192
#define BM     128            // rows per CTA (blockIdx.y)
#define BN     128            // symbol cols per CTA (blockIdx.x)
#define BK     32             // k-chunk per stage
#define NCHUNK (D2 / BK)      // 32
#define RECORDS 256           // per-row top2 records = 64 col tiles * 4 warpN
#define MARGIN 0.5f

// output packing (reference tuple order, flattened, float32)
#define ZQ_OFF   0ULL
#define LOSS_OFF 16777216ULL
#define MIDX_OFF 16777217ULL
#define NCB_OFF  16793601ULL
#define NCS_OFF  25182209ULL
#define NEA_OFF  25190401ULL

// smem stage layout:
//  z   : 128 rows x 128B fp32 (k-permuted + XOR row swizzle) @ 0      (16KB)
//  cb  : 128 rows x 128B fp32 (same)                          @ 16384 (16KB)
//  ctx : 128 rows x 64B bf16 (pair-permuted)                  @ 32768 (8KB)
//  gw  : 128 rows x 64B bf16 (same)                           @ 40960 (8KB)
#define SEG_Z   0
#define SEG_CB  16384
#define SEG_C   32768
#define SEG_GW  40960
#define STAGE   49152
#define NSTAGE  3
#define SMEM_BYTES (NSTAGE * STAGE)   // 147456

// ---------------- scratch (device globals, no allocation) ----------------
__device__ float  g_cnorm[KSYM];
__device__ float  g_top2v[(size_t)N_ROWS * RECORDS * 2];
__device__ int    g_top2i[(size_t)N_ROWS * RECORDS * 2];
__device__ int    g_midx[N_ROWS];
__device__ int    g_counts[KSYM];
__device__ double g_loss;
__device__ float  g_cs[KSYM];
// k-permuted operand copies
__device__ float    g_zp[(size_t)N_ROWS * D2];        // 64MB fp32 z (concat, permuted)
__device__ float    g_cbp[(size_t)KSYM * D2];         // 32MB fp32 codebook (permuted)
__device__ uint32_t g_ctxp[(size_t)N_ROWS * D2 / 2];  // 32MB bf16x2 ctx (permuted)
__device__ uint32_t g_gwp[(size_t)KSYM * D2 / 2];     // 16MB bf16x2 gate_w (permuted)

// ---------------- helpers ----------------
__device__ __forceinline__ uint32_t smem_to_u32(const void* p) {
    uint32_t a;
    asm("{ .reg .u64 t; cvta.to.shared.u64 t, %1; cvt.u32.u64 %0, t; }" : "=r"(a) : "l"(p));
    return a;
}
__device__ __forceinline__ float tanh_approx(float x) {
    float y; asm("tanh.approx.f32 %0, %1;" : "=f"(y) : "f"(x)); return y;
}
__device__ __forceinline__ void cp16(uint32_t dst, const void* src) {
    asm volatile("cp.async.cg.shared.global [%0], [%1], 16;" :: "r"(dst), "l"(src));
}
__device__ __forceinline__ uint4 lds128(uint32_t addr) {
    uint4 v;
    asm volatile("ld.shared.v4.b32 {%0,%1,%2,%3}, [%4];"
        : "=r"(v.x), "=r"(v.y), "=r"(v.z), "=r"(v.w) : "r"(addr));
    return v;
}
__device__ __forceinline__ void mma_tf32(float* d, const uint32_t* a, const uint32_t* b) {
    asm volatile(
        "mma.sync.aligned.m16n8k8.row.col.f32.tf32.tf32.f32 "
        "{%0,%1,%2,%3}, {%4,%5,%6,%7}, {%8,%9}, {%0,%1,%2,%3};"
        : "+f"(d[0]), "+f"(d[1]), "+f"(d[2]), "+f"(d[3])
        : "r"(a[0]), "r"(a[1]), "r"(a[2]), "r"(a[3]), "r"(b[0]), "r"(b[1]));
}
__device__ __forceinline__ void mma_bf16(float* d, const uint32_t* a, const uint32_t* b) {
    asm volatile(
        "mma.sync.aligned.m16n8k16.row.col.f32.bf16.bf16.f32 "
        "{%0,%1,%2,%3}, {%4,%5,%6,%7}, {%8,%9}, {%0,%1,%2,%3};"
        : "+f"(d[0]), "+f"(d[1]), "+f"(d[2]), "+f"(d[3])
        : "r"(a[0]), "r"(a[1]), "r"(a[2]), "r"(a[3]), "r"(b[0]), "r"(b[1]));
}

// ---------------- 0a. fp32 permute kernels ----------------
// word k -> chunk c=k>>5, w=k&31, permuted slot c*32 + (w&3)*8 + (w>>2)
__global__ void perm_z_kernel(const float* __restrict__ zr, const float* __restrict__ zi) {
    size_t total = (size_t)N_ROWS * D2;
    size_t stride = (size_t)gridDim.x * blockDim.x;
    for (size_t i = (size_t)blockIdx.x * blockDim.x + threadIdx.x; i < total; i += stride) {
        int n = (int)(i >> 10), k = (int)(i & 1023);
        float v = (k < 512) ? zr[(size_t)n * 512 + k] : zi[(size_t)n * 512 + k - 512];
        int c = k >> 5, w = k & 31;
        g_zp[(size_t)n * 1024 + c * 32 + (w & 3) * 8 + (w >> 2)] = v;
    }
}
__global__ void perm_cb_kernel(const float* __restrict__ cb) {
    size_t total = (size_t)KSYM * D2;
    size_t stride = (size_t)gridDim.x * blockDim.x;
    for (size_t i = (size_t)blockIdx.x * blockDim.x + threadIdx.x; i < total; i += stride) {
        int n = (int)(i >> 10), k = (int)(i & 1023);
        int c = k >> 5, w = k & 31;
        g_cbp[(size_t)n * 1024 + c * 32 + (w & 3) * 8 + (w >> 2)] = cb[i];
    }
}
// ---------------- 0b. bf16 pair-permute kernels ----------------
// pair p (k=2p,2p+1) -> chunk c=p>>4, pp=p&15, slot c*16 + (pp&3)*4 + (pp>>2) (uint32 words)
__global__ void perm_ctx_kernel(const float* __restrict__ cr, const float* __restrict__ ci) {
    size_t total = (size_t)N_ROWS * 512;
    size_t stride = (size_t)gridDim.x * blockDim.x;
    for (size_t i = (size_t)blockIdx.x * blockDim.x + threadIdx.x; i < total; i += stride) {
        int n = (int)(i >> 9), p = (int)(i & 511);
        int k = 2 * p;
        float a, b;
        if (k < 512) { a = cr[(size_t)n * 512 + k]; b = cr[(size_t)n * 512 + k + 1]; }
        else         { a = ci[(size_t)n * 512 + k - 512]; b = ci[(size_t)n * 512 + k - 511]; }
        __nv_bfloat162 h = __floats2bfloat162_rn(a, b);
        uint32_t pack; *(__nv_bfloat162*)&pack = h;
        int c = p >> 4, pp = p & 15;
        g_ctxp[(size_t)n * 512 + c * 16 + (pp & 3) * 4 + (pp >> 2)] = pack;
    }
}
__global__ void perm_gw_kernel(const float* __restrict__ gw) {
    size_t total = (size_t)KSYM * 512;
    size_t stride = (size_t)gridDim.x * blockDim.x;
    for (size_t i = (size_t)blockIdx.x * blockDim.x + threadIdx.x; i < total; i += stride) {
        int n = (int)(i >> 9), p = (int)(i & 511);
        float a = gw[(size_t)n * 1024 + 2 * p];
        float b = gw[(size_t)n * 1024 + 2 * p + 1];
        __nv_bfloat162 h = __floats2bfloat162_rn(a, b);
        uint32_t pack; *(__nv_bfloat162*)&pack = h;
        int c = p >> 4, pp = p & 15;
        g_gwp[(size_t)n * 512 + c * 16 + (pp & 3) * 4 + (pp >> 2)] = pack;
    }
}

// ---------------- 1. codebook row norms (fp64 accumulate) ----------------
__global__ void prep_cnorm_kernel(const float* __restrict__ codebook) {
    int k = blockIdx.x;
    const float* row = codebook + (size_t)k * D2;
    double s = 0.0;
    for (int t = threadIdx.x; t < D2; t += 256) { double v = (double)row[t]; s += v * v; }
    __shared__ double sh[256];
    sh[threadIdx.x] = s; __syncthreads();
    for (int o = 128; o > 0; o >>= 1) { if (threadIdx.x < o) sh[threadIdx.x] += sh[threadIdx.x + o]; __syncthreads(); }
    if (threadIdx.x == 0) g_cnorm[k] = (float)sh[0];
}

// ---------------- 2. init ----------------
__global__ void init_kernel(const float* __restrict__ embed_avg, float* __restrict__ out) {
    size_t total = (size_t)KSYM * D2;
    size_t stride = (size_t)gridDim.x * blockDim.x;
    size_t j = (size_t)blockIdx.x * blockDim.x + threadIdx.x;
    for (size_t i = j; i < total; i += stride) out[NEA_OFF + i] = 0.99f * embed_avg[i];
    if (j < KSYM) g_counts[j] = 0;
    if (j == 0) g_loss = 0.0;
}

// ---------------- 3. fused dual-GEMM score kernel ----------------
// 512 threads, 16 warps: warp grid 4(M) x 4(N), warp tile 32x32, CTA tile 128x128.
// All fragment loads are LDS.128 from k-permuted smem layouts.
__global__ __launch_bounds__(512, 1)
void score_mma_kernel(const int* __restrict__ prev_idx,
                      const float* __restrict__ adjacency,
                      const float* __restrict__ gate_b) {
    extern __shared__ char smem[];
    const uint32_t sbu = smem_to_u32(smem);
    const int tid   = threadIdx.x;
    const int wid   = tid >> 5;
    const int lane  = tid & 31;
    const int g     = lane >> 2;      // group id 0..7
    const int tig   = lane & 3;       // thread-in-group
    const int warpM = wid >> 2;       // 0..3 (32 rows)
    const int warpN = wid & 3;        // 0..3 (32 cols)
    const int rowBase = blockIdx.y * BM;
    const int cbase   = blockIdx.x * BN;

    // ---- stage loader: 6 x 16B per thread (all contiguous global reads) ----
    auto load_stage = [&](int c, int buf) {
        const uint32_t bb = sbu + (uint32_t)buf * STAGE;
#pragma unroll
        for (int i = 0; i < 2; i++) {
            int q = tid + (i << 9);
            int r = q >> 3, q8 = q & 7;
            uint32_t so = (uint32_t)(r * 128 + ((q8 * 16) ^ ((r & 7) << 4)));
            cp16(bb + SEG_Z + so, g_zp + (size_t)(rowBase + r) * 1024 + c * 32 + q8 * 4);
            cp16(bb + SEG_CB + so, g_cbp + (size_t)(cbase + r) * 1024 + c * 32 + q8 * 4);
        }
        {
            int r = tid >> 2, qq = tid & 3;
            uint32_t so = (uint32_t)(r * 64 + qq * 16);
            cp16(bb + SEG_C + so, g_ctxp + (size_t)(rowBase + r) * 512 + c * 16 + qq * 4);
            cp16(bb + SEG_GW + so, g_gwp + (size_t)(cbase + r) * 512 + c * 16 + qq * 4);
        }
        asm volatile("cp.async.commit_group;" ::: "memory");
    };

    float accd[2][4][4], accg[2][4][4];
#pragma unroll
    for (int mt = 0; mt < 2; mt++)
#pragma unroll
        for (int nt = 0; nt < 4; nt++)
#pragma unroll
            for (int e = 0; e < 4; e++) { accd[mt][nt][e] = 0.f; accg[mt][nt][e] = 0.f; }

    // fragment base addresses (per 8-row subgroup s: rows g, g+8, g+16, g+24)
    uint32_t aZ[4], aB[4], aC[4], aG[4];
#pragma unroll
    for (int s = 0; s < 4; s++) {
        uint32_t granA = (uint32_t)(((2 * tig) ^ g) << 4);   // j=0 granule; j=1 -> ^16
        aZ[s] = SEG_Z  + (uint32_t)(warpM * 32 + g + 8 * s) * 128 + granA;
        aB[s] = SEG_CB + (uint32_t)(warpN * 32 + g + 8 * s) * 128 + granA;
        aC[s] = SEG_C  + (uint32_t)(warpM * 32 + g + 8 * s) * 64 + tig * 16;
        aG[s] = SEG_GW + (uint32_t)(warpN * 32 + g + 8 * s) * 64 + tig * 16;
    }

    // prologue: 2 stages in flight
    load_stage(0, 0);
    load_stage(1, 1);

    int buf = 0;
    for (int c = 0; c < NCHUNK; ++c) {
        if (c + 1 < NCHUNK) asm volatile("cp.async.wait_group 1;" ::: "memory");
        else                asm volatile("cp.async.wait_group 0;" ::: "memory");
        __syncthreads();
        if (c + 2 < NCHUNK) {
            int nb = buf + 2; if (nb >= NSTAGE) nb -= NSTAGE;
            load_stage(c + 2, nb);
        }
        const uint32_t bb = sbu + (uint32_t)buf * STAGE;

        // ---- dot GEMM (tf32): two j-halves, each 2 k8-steps ----
#pragma unroll
        for (int j = 0; j < 2; j++) {
            uint32_t az[4][4], bc[4][4];
#pragma unroll
            for (int s = 0; s < 4; s++) {
                uint4 vz = lds128(bb + (aZ[s] ^ (uint32_t)(j << 4)));
                az[s][0] = vz.x; az[s][1] = vz.y; az[s][2] = vz.z; az[s][3] = vz.w;
                uint4 vb = lds128(bb + (aB[s] ^ (uint32_t)(j << 4)));
                bc[s][0] = vb.x; bc[s][1] = vb.y; bc[s][2] = vb.z; bc[s][3] = vb.w;
            }
#pragma unroll
            for (int k2 = 0; k2 < 2; k2++) {
                uint32_t af0[4] = {az[0][2*k2], az[1][2*k2], az[0][2*k2+1], az[1][2*k2+1]};
                uint32_t af1[4] = {az[2][2*k2], az[3][2*k2], az[2][2*k2+1], az[3][2*k2+1]};
#pragma unroll
                for (int nt = 0; nt < 4; nt++) {
                    uint32_t bf2[2] = {bc[nt][2*k2], bc[nt][2*k2+1]};
                    mma_tf32(accd[0][nt], af0, bf2);
                    mma_tf32(accd[1][nt], af1, bf2);
                }
            }
        }

        // ---- gate GEMM (bf16): 2 k16-steps, fragments for whole chunk in 8 LDS.128 ----
        {
            uint32_t ax[4][4], bx[4][4];
#pragma unroll
            for (int s = 0; s < 4; s++) {
                uint4 vc = lds128(bb + aC[s]);
                ax[s][0] = vc.x; ax[s][1] = vc.y; ax[s][2] = vc.z; ax[s][3] = vc.w;
                uint4 vw = lds128(bb + aG[s]);
                bx[s][0] = vw.x; bx[s][1] = vw.y; bx[s][2] = vw.z; bx[s][3] = vw.w;
            }
#pragma unroll
            for (int t = 0; t < 2; t++) {
                uint32_t af0[4] = {ax[0][2*t], ax[1][2*t], ax[0][2*t+1], ax[1][2*t+1]};
                uint32_t af1[4] = {ax[2][2*t], ax[3][2*t], ax[2][2*t+1], ax[3][2*t+1]};
#pragma unroll
                for (int nt = 0; nt < 4; nt++) {
                    uint32_t bf2[2] = {bx[nt][2*t], bx[nt][2*t+1]};
                    mma_bf16(accg[0][nt], af0, bf2);
                    mma_bf16(accg[1][nt], af1, bf2);
                }
            }
        }
        buf++; if (buf >= NSTAGE) buf = 0;
    }

    // ---- epilogue: bias + per-row top-2 ----
    float cnv[4][2], gbv[4][2];
#pragma unroll
    for (int nt = 0; nt < 4; nt++)
#pragma unroll
        for (int e = 0; e < 2; e++) {
            int col = cbase + warpN * 32 + nt * 8 + 2 * tig + e;
            cnv[nt][e] = g_cnorm[col];
            gbv[nt][e] = gate_b[col];
        }

    const float INF = __int_as_float(0x7f800000);
#pragma unroll
    for (int mt = 0; mt < 2; mt++)
#pragma unroll
        for (int hi = 0; hi < 2; hi++) {
            int rowg = rowBase + warpM * 32 + mt * 16 + hi * 8 + g;
            const float* adjr = adjacency + (size_t)prev_idx[rowg] * KSYM;
            float V1 = INF, V2 = INF;
            int   I1 = 0x7fffffff, I2 = 0x7fffffff;
#pragma unroll
            for (int nt = 0; nt < 4; nt++)
#pragma unroll
                for (int e = 0; e < 2; e++) {
                    int col = cbase + warpN * 32 + nt * 8 + 2 * tig + e;
                    float dot = accd[mt][nt][hi * 2 + e];
                    float gt  = accg[mt][nt][hi * 2 + e];
                    float adj = __ldg(adjr + col);
                    float sig = 1.f / (1.f + __expf(-adj));
                    float th  = tanh_approx(gt + gbv[nt][e]);
                    float s = fmaf(-2.f, dot, cnv[nt][e]) - 0.8f * sig * fmaf(0.5f, th, 1.f);
                    if (s < V1 || (s == V1 && col < I1)) { V2 = V1; I2 = I1; V1 = s; I1 = col; }
                    else if (s < V2 || (s == V2 && col < I2)) { V2 = s; I2 = col; }
                }
#pragma unroll
            for (int off = 1; off <= 2; off <<= 1) {
                float ov1 = __shfl_xor_sync(0xffffffffu, V1, off);
                int   oi1 = __shfl_xor_sync(0xffffffffu, I1, off);
                float ov2 = __shfl_xor_sync(0xffffffffu, V2, off);
                int   oi2 = __shfl_xor_sync(0xffffffffu, I2, off);
                if (ov1 < V1 || (ov1 == V1 && oi1 < I1)) {
                    float nv2; int ni2;
                    if (V1 < ov2 || (V1 == ov2 && I1 < oi2)) { nv2 = V1; ni2 = I1; }
                    else { nv2 = ov2; ni2 = oi2; }
                    V1 = ov1; I1 = oi1; V2 = nv2; I2 = ni2;
                } else if (ov1 < V2 || (ov1 == V2 && oi1 < I2)) {
                    V2 = ov1; I2 = oi1;
                }
            }
            if (tig == 0) {
                size_t o = ((size_t)rowg * RECORDS + blockIdx.x * 4 + warpN) * 2;
                g_top2v[o] = V1;  g_top2i[o] = I1;
                g_top2v[o + 1] = V2; g_top2i[o + 1] = I2;
            }
        }
}

// ---------------- 4. merge top-2s; fp64 refinement for near-ties ----------------
__global__ void merge_refine_kernel(const float* __restrict__ z_real,  const float* __restrict__ z_imag,
                                    const float* __restrict__ ctx_real, const float* __restrict__ ctx_imag,
                                    const int*   __restrict__ prev_idx,
                                    const float* __restrict__ codebook, const float* __restrict__ adjacency,
                                    const float* __restrict__ gate_w,   const float* __restrict__ gate_b,
                                    float* __restrict__ out) {
    int gwarp = (blockIdx.x * blockDim.x + threadIdx.x) >> 5;
    int lane = threadIdx.x & 31;
    if (gwarp >= N_ROWS) return;
    const int n = gwarp;
    const float INF = __int_as_float(0x7f800000);

    float v1 = INF, v2 = INF;
    int i1 = 0x7fffffff, i2 = 0x7fffffff;
    const size_t base = (size_t)n * (RECORDS * 2);
#pragma unroll
    for (int q = 0; q < 16; q++) {
        int e = lane + q * 32;
        float v = g_top2v[base + e];
        int ix  = g_top2i[base + e];
        if (v < v1 || (v == v1 && ix < i1)) { v2 = v1; i2 = i1; v1 = v; i1 = ix; }
        else if (v < v2 || (v == v2 && ix < i2)) { v2 = v; i2 = ix; }
    }
#pragma unroll
    for (int off = 16; off; off >>= 1) {
        float ov1 = __shfl_down_sync(0xffffffffu, v1, off);
        float ov2 = __shfl_down_sync(0xffffffffu, v2, off);
        int   oi1 = __shfl_down_sync(0xffffffffu, i1, off);
        int   oi2 = __shfl_down_sync(0xffffffffu, i2, off);
        if (ov1 < v1 || (ov1 == v1 && oi1 < i1)) { v2 = v1; i2 = i1; v1 = ov1; i1 = oi1; }
        else if (ov1 < v2 || (ov1 == v2 && oi1 < i2)) { v2 = ov1; i2 = oi1; }
        if (ov2 < v1 || (ov2 == v1 && oi2 < i1)) { v2 = v1; i2 = i1; v1 = ov2; i1 = oi2; }
        else if (ov2 < v2 || (ov2 == v2 && oi2 < i2)) { v2 = ov2; i2 = oi2; }
    }
    float bv1 = __shfl_sync(0xffffffffu, v1, 0);
    float bv2 = __shfl_sync(0xffffffffu, v2, 0);
    int   bi1 = __shfl_sync(0xffffffffu, i1, 0);
    int   bi2 = __shfl_sync(0xffffffffu, i2, 0);

    int pick = bi1;
    if (bv2 - bv1 < MARGIN) {
        double a0 = 0, a1 = 0, a2 = 0, a3 = 0, a4 = 0, a5 = 0;
        for (int t = lane; t < D2; t += 32) {
            double zt = (t < 512) ? (double)z_real[(size_t)n * 512 + t]
                                  : (double)z_imag[(size_t)n * 512 + t - 512];
            double xt = (t < 512) ? (double)ctx_real[(size_t)n * 512 + t]
                                  : (double)ctx_imag[(size_t)n * 512 + t - 512];
            double c1 = (double)codebook[(size_t)bi1 * D2 + t];
            double w1 = (double)gate_w[(size_t)bi1 * D2 + t];
            double c2 = (double)codebook[(size_t)bi2 * D2 + t];
            double w2 = (double)gate_w[(size_t)bi2 * D2 + t];
            a0 += c1 * c1; a1 += zt * c1; a2 += xt * w1;
            a3 += c2 * c2; a4 += zt * c2; a5 += xt * w2;
        }
        for (int o = 16; o; o >>= 1) {
            a0 += __shfl_down_sync(0xffffffffu, a0, o);
            a1 += __shfl_down_sync(0xffffffffu, a1, o);
            a2 += __shfl_down_sync(0xffffffffu, a2, o);
            a3 += __shfl_down_sync(0xffffffffu, a3, o);
            a4 += __shfl_down_sync(0xffffffffu, a4, o);
            a5 += __shfl_down_sync(0xffffffffu, a5, o);
        }
        if (lane == 0) {
            int p = prev_idx[n];
            double ad1 = (double)adjacency[(size_t)p * KSYM + bi1];
            double ad2 = (double)adjacency[(size_t)p * KSYM + bi2];
            double gb1 = (double)gate_b[bi1];
            double gb2 = (double)gate_b[bi2];
            double d1 = a0 - 2.0 * a1 - 0.8 * (1.0 / (1.0 + exp(-ad1))) * (1.0 + 0.5 * tanh(a2 + gb1));
            double d2 = a3 - 2.0 * a4 - 0.8 * (1.0 / (1.0 + exp(-ad2))) * (1.0 + 0.5 * tanh(a5 + gb2));
            pick = (d2 < d1 || (d2 == d1 && bi2 < bi1)) ? bi2 : bi1;
        }
        pick = __shfl_sync(0xffffffffu, pick, 0);
    }
    if (lane == 0) {
        g_midx[n] = pick;
        out[MIDX_OFF + n] = (float)pick;
        atomicAdd(&g_counts[pick], 1);
    }
}

// ---------------- 5. z_q gather, embed_sum scatter, loss ----------------
__global__ void scatter_kernel(const float* __restrict__ z_real, const float* __restrict__ z_imag,
                               const float* __restrict__ codebook, float* __restrict__ out) {
    const int n = blockIdx.x;
    const int m = g_midx[n];
    const int tid = threadIdx.x;
    const int d0 = tid * 4;

    float4 c = *(const float4*)(codebook + (size_t)m * D2 + d0);
    float4 z;
    if (d0 < 512) z = *(const float4*)(z_real + (size_t)n * 512 + d0);
    else          z = *(const float4*)(z_imag + (size_t)n * 512 + d0 - 512);

    *(float4*)(out + ZQ_OFF + (size_t)n * D2 + d0) = c;

    float* ea = out + NEA_OFF + (size_t)m * D2 + d0;
    atomicAdd(ea + 0, 0.01f * z.x);
    atomicAdd(ea + 1, 0.01f * z.y);
    atomicAdd(ea + 2, 0.01f * z.z);
    atomicAdd(ea + 3, 0.01f * z.w);

    float dx = c.x - z.x, dy = c.y - z.y, dz = c.z - z.z, dw = c.w - z.w;
    float lsum = dx * dx + dy * dy + dz * dz + dw * dw;

    __shared__ float sh[256];
    sh[tid] = lsum; __syncthreads();
    for (int o = 128; o > 0; o >>= 1) { if (tid < o) sh[tid] += sh[tid + o]; __syncthreads(); }
    if (tid == 0) atomicAdd(&g_loss, (double)sh[0]);
}

// ---------------- 6a. cluster-size EMA, cs, loss ----------------
__global__ void finalize_a_kernel(const float* __restrict__ cluster_size, float* __restrict__ out) {
    const int tid = threadIdx.x;  // 1024 threads
    float ncs[8];
    float psum = 0.f;
#pragma unroll
    for (int q = 0; q < 8; q++) {
        int k = tid * 8 + q;
        float v = cluster_size[k] * 0.99f + 0.01f * (float)g_counts[k];
        ncs[q] = v;
        out[NCS_OFF + k] = v;
        psum += v;
    }
    __shared__ float sh[1024];
    sh[tid] = psum; __syncthreads();
    for (int o = 512; o > 0; o >>= 1) { if (tid < o) sh[tid] += sh[tid + o]; __syncthreads(); }
    float ntot = sh[0];
#pragma unroll
    for (int q = 0; q < 8; q++) {
        float cs = (ncs[q] + 1e-6f) / (ntot + (float)KSYM * 1e-6f) * ntot;
        g_cs[tid * 8 + q] = cs;
    }
    if (tid == 0) out[LOSS_OFF] = (float)(1.25 * g_loss / 16777216.0);
}

// ---------------- 6b. new_codebook = new_embed_avg / cs ----------------
__global__ void finalize_b_kernel(float* __restrict__ out) {
    size_t total = (size_t)KSYM * D2;
    size_t stride = (size_t)gridDim.x * blockDim.x;
    for (size_t i = (size_t)blockIdx.x * blockDim.x + threadIdx.x; i < total; i += stride) {
        int k = (int)(i >> 10);
        out[NCB_OFF + i] = out[NEA_OFF + i] / g_cs[k];
    }
}

// ---------------- entry ----------------
extern "C" void kernel_launch(void* const* d_in, const int* in_sizes, int n_in,
                              void* d_out, int out_size) {
    const float* z_real     = (const float*)d_in[0];
    const float* z_imag     = (const float*)d_in[1];
    const float* ctx_real   = (const float*)d_in[2];
    const float* ctx_imag   = (const float*)d_in[3];
    const int*   prev_idx   = (const int*)d_in[4];
    const float* codebook   = (const float*)d_in[5];
    const float* adjacency  = (const float*)d_in[6];
    const float* gate_w     = (const float*)d_in[7];
    const float* gate_b     = (const float*)d_in[8];
    const float* cluster_sz = (const float*)d_in[9];
    const float* embed_avg  = (const float*)d_in[10];
    float* out = (float*)d_out;

    cudaFuncSetAttribute(score_mma_kernel, cudaFuncAttributeMaxDynamicSharedMemorySize, SMEM_BYTES);

    perm_z_kernel<<<4096, 256>>>(z_real, z_imag);
    perm_cb_kernel<<<4096, 256>>>(codebook);
    perm_ctx_kernel<<<4096, 256>>>(ctx_real, ctx_imag);
    perm_gw_kernel<<<4096, 256>>>(gate_w);
    prep_cnorm_kernel<<<KSYM, 256>>>(codebook);
    init_kernel<<<8192, 256>>>(embed_avg, out);
    // blockIdx.x = column tile (fast) so codebook/gate_w stay L2-resident
    score_mma_kernel<<<dim3(KSYM / BN, N_ROWS / BM), 512, SMEM_BYTES>>>(
        prev_idx, adjacency, gate_b);
    merge_refine_kernel<<<N_ROWS / 8, 256>>>(z_real, z_imag, ctx_real, ctx_imag,
                                             prev_idx, codebook, adjacency, gate_w, gate_b, out);
    scatter_kernel<<<N_ROWS, 256>>>(z_real, z_imag, codebook, out);
    finalize_a_kernel<<<1, 1024>>>(cluster_sz, out);
    finalize_b_kernel<<<8192, 256>>>(out);
}

// round 7
// speedup vs baseline: 1.4241x; 1.1931x over previous
#include <cuda_runtime.h>
#include <cuda_bf16.h>
#include <cuda_fp16.h>
#include <math.h>
#include <stdint.h>

// ---------------- problem constants ----------------
#define N_ROWS 16384
#define D2     1024
#define KSYM   8192
#define BM     128            // rows per CTA (blockIdx.y)
#define BN     128            // symbol cols per CTA (blockIdx.x)
#define BK     32             // k-chunk per stage
#define NCHUNK (D2 / BK)      // 32
#define RECORDS 256           // per-row top2 records = 64 col tiles * 4 warpN
#define MARGIN 0.5f

// output packing (reference tuple order, flattened, float32)
#define ZQ_OFF   0ULL
#define LOSS_OFF 16777216ULL
#define MIDX_OFF 16777217ULL
#define NCB_OFF  16793601ULL
#define NCS_OFF  25182209ULL
#define NEA_OFF  25190401ULL

// smem stage layout: four 16-bit segments, 128 rows x 64B each (pair-permuted)
#define SEG_Z   0
#define SEG_CB  8192
#define SEG_C   16384
#define SEG_GW  24576
#define STAGE   32768
#define NSTAGE  3
#define SMEM_BYTES (NSTAGE * STAGE)   // 98304

// ---------------- scratch (device globals, no allocation) ----------------
__device__ float  g_cnorm[KSYM];
__device__ float  g_top2v[(size_t)N_ROWS * RECORDS * 2];
__device__ int    g_top2i[(size_t)N_ROWS * RECORDS * 2];
__device__ int    g_midx[N_ROWS];
__device__ int    g_counts[KSYM];
__device__ double g_loss;
__device__ float  g_cs[KSYM];
// pair-permuted 16-bit operand copies (packed as uint32 = 2 elems)
__device__ uint32_t g_zp[(size_t)N_ROWS * D2 / 2];    // fp16x2 z (concat, permuted)
__device__ uint32_t g_cbp[(size_t)KSYM * D2 / 2];     // fp16x2 codebook (permuted)
__device__ uint32_t g_ctxp[(size_t)N_ROWS * D2 / 2];  // bf16x2 ctx (permuted)
__device__ uint32_t g_gwp[(size_t)KSYM * D2 / 2];     // bf16x2 gate_w (permuted)

// ---------------- helpers ----------------
__device__ __forceinline__ uint32_t smem_to_u32(const void* p) {
    uint32_t a;
    asm("{ .reg .u64 t; cvta.to.shared.u64 t, %1; cvt.u32.u64 %0, t; }" : "=r"(a) : "l"(p));
    return a;
}
__device__ __forceinline__ float tanh_approx(float x) {
    float y; asm("tanh.approx.f32 %0, %1;" : "=f"(y) : "f"(x)); return y;
}
__device__ __forceinline__ void cp16(uint32_t dst, const void* src) {
    asm volatile("cp.async.cg.shared.global [%0], [%1], 16;" :: "r"(dst), "l"(src));
}
__device__ __forceinline__ uint4 lds128(uint32_t addr) {
    uint4 v;
    asm volatile("ld.shared.v4.b32 {%0,%1,%2,%3}, [%4];"
        : "=r"(v.x), "=r"(v.y), "=r"(v.z), "=r"(v.w) : "r"(addr));
    return v;
}
__device__ __forceinline__ void mma_f16(float* d, const uint32_t* a, const uint32_t* b) {
    asm volatile(
        "mma.sync.aligned.m16n8k16.row.col.f32.f16.f16.f32 "
        "{%0,%1,%2,%3}, {%4,%5,%6,%7}, {%8,%9}, {%0,%1,%2,%3};"
        : "+f"(d[0]), "+f"(d[1]), "+f"(d[2]), "+f"(d[3])
        : "r"(a[0]), "r"(a[1]), "r"(a[2]), "r"(a[3]), "r"(b[0]), "r"(b[1]));
}
__device__ __forceinline__ void mma_bf16(float* d, const uint32_t* a, const uint32_t* b) {
    asm volatile(
        "mma.sync.aligned.m16n8k16.row.col.f32.bf16.bf16.f32 "
        "{%0,%1,%2,%3}, {%4,%5,%6,%7}, {%8,%9}, {%0,%1,%2,%3};"
        : "+f"(d[0]), "+f"(d[1]), "+f"(d[2]), "+f"(d[3])
        : "r"(a[0]), "r"(a[1]), "r"(a[2]), "r"(a[3]), "r"(b[0]), "r"(b[1]));
}

// pair p -> chunk c=p>>4, pp=p&15, slot c*16 + (pp&3)*4 + (pp>>2)  (uint32 words)
__device__ __forceinline__ int pslot(int p) {
    int c = p >> 4, pp = p & 15;
    return c * 16 + (pp & 3) * 4 + (pp >> 2);
}

// ---------------- 0. permute+convert prep kernels ----------------
__global__ void perm_z_kernel(const float* __restrict__ zr, const float* __restrict__ zi) {
    size_t total = (size_t)N_ROWS * 512;
    size_t stride = (size_t)gridDim.x * blockDim.x;
    for (size_t i = (size_t)blockIdx.x * blockDim.x + threadIdx.x; i < total; i += stride) {
        int n = (int)(i >> 9), p = (int)(i & 511);
        int k = 2 * p;
        float a, b;
        if (k < 512) { a = zr[(size_t)n * 512 + k]; b = zr[(size_t)n * 512 + k + 1]; }
        else         { a = zi[(size_t)n * 512 + k - 512]; b = zi[(size_t)n * 512 + k - 511]; }
        __half2 h = __floats2half2_rn(a, b);
        uint32_t pack; *(__half2*)&pack = h;
        g_zp[(size_t)n * 512 + pslot(p)] = pack;
    }
}
__global__ void perm_cb_kernel(const float* __restrict__ cb) {
    size_t total = (size_t)KSYM * 512;
    size_t stride = (size_t)gridDim.x * blockDim.x;
    for (size_t i = (size_t)blockIdx.x * blockDim.x + threadIdx.x; i < total; i += stride) {
        int n = (int)(i >> 9), p = (int)(i & 511);
        __half2 h = __floats2half2_rn(cb[(size_t)n * 1024 + 2 * p], cb[(size_t)n * 1024 + 2 * p + 1]);
        uint32_t pack; *(__half2*)&pack = h;
        g_cbp[(size_t)n * 512 + pslot(p)] = pack;
    }
}
__global__ void perm_ctx_kernel(const float* __restrict__ cr, const float* __restrict__ ci) {
    size_t total = (size_t)N_ROWS * 512;
    size_t stride = (size_t)gridDim.x * blockDim.x;
    for (size_t i = (size_t)blockIdx.x * blockDim.x + threadIdx.x; i < total; i += stride) {
        int n = (int)(i >> 9), p = (int)(i & 511);
        int k = 2 * p;
        float a, b;
        if (k < 512) { a = cr[(size_t)n * 512 + k]; b = cr[(size_t)n * 512 + k + 1]; }
        else         { a = ci[(size_t)n * 512 + k - 512]; b = ci[(size_t)n * 512 + k - 511]; }
        __nv_bfloat162 h = __floats2bfloat162_rn(a, b);
        uint32_t pack; *(__nv_bfloat162*)&pack = h;
        g_ctxp[(size_t)n * 512 + pslot(p)] = pack;
    }
}
__global__ void perm_gw_kernel(const float* __restrict__ gw) {
    size_t total = (size_t)KSYM * 512;
    size_t stride = (size_t)gridDim.x * blockDim.x;
    for (size_t i = (size_t)blockIdx.x * blockDim.x + threadIdx.x; i < total; i += stride) {
        int n = (int)(i >> 9), p = (int)(i & 511);
        __nv_bfloat162 h = __floats2bfloat162_rn(gw[(size_t)n * 1024 + 2 * p], gw[(size_t)n * 1024 + 2 * p + 1]);
        uint32_t pack; *(__nv_bfloat162*)&pack = h;
        g_gwp[(size_t)n * 512 + pslot(p)] = pack;
    }
}

// ---------------- 1. codebook row norms (fp64 accumulate) ----------------
__global__ void prep_cnorm_kernel(const float* __restrict__ codebook) {
    int k = blockIdx.x;
    const float* row = codebook + (size_t)k * D2;
    double s = 0.0;
    for (int t = threadIdx.x; t < D2; t += 256) { double v = (double)row[t]; s += v * v; }
    __shared__ double sh[256];
    sh[threadIdx.x] = s; __syncthreads();
    for (int o = 128; o > 0; o >>= 1) { if (threadIdx.x < o) sh[threadIdx.x] += sh[threadIdx.x + o]; __syncthreads(); }
    if (threadIdx.x == 0) g_cnorm[k] = (float)sh[0];
}

// ---------------- 2. init ----------------
__global__ void init_kernel(const float* __restrict__ embed_avg, float* __restrict__ out) {
    size_t total = (size_t)KSYM * D2;
    size_t stride = (size_t)gridDim.x * blockDim.x;
    size_t j = (size_t)blockIdx.x * blockDim.x + threadIdx.x;
    for (size_t i = j; i < total; i += stride) out[NEA_OFF + i] = 0.99f * embed_avg[i];
    if (j < KSYM) g_counts[j] = 0;
    if (j == 0) g_loss = 0.0;
}

// ---------------- 3. fused dual-GEMM score kernel (fp16 dot + bf16 gate) ----------------
// 512 threads, 16 warps: warp grid 4(M) x 4(N), warp tile 32x32, CTA tile 128x128.
__global__ __launch_bounds__(512, 1)
void score_mma_kernel(const int* __restrict__ prev_idx,
                      const float* __restrict__ adjacency,
                      const float* __restrict__ gate_b) {
    extern __shared__ char smem[];
    const uint32_t sbu = smem_to_u32(smem);
    const int tid   = threadIdx.x;
    const int wid   = tid >> 5;
    const int lane  = tid & 31;
    const int g     = lane >> 2;      // group id 0..7
    const int tig   = lane & 3;       // thread-in-group
    const int warpM = wid >> 2;       // 0..3 (32 rows)
    const int warpN = wid & 3;        // 0..3 (32 cols)
    const int rowBase = blockIdx.y * BM;
    const int cbase   = blockIdx.x * BN;

    // ---- stage loader: 4 x 16B per thread, all contiguous ----
    auto load_stage = [&](int c, int buf) {
        const uint32_t bb = sbu + (uint32_t)buf * STAGE;
        int r = tid >> 2, qq = tid & 3;
        uint32_t so = (uint32_t)(r * 64 + qq * 16);
        size_t gr = (size_t)(rowBase + r) * 512 + c * 16 + qq * 4;
        size_t gc = (size_t)(cbase + r) * 512 + c * 16 + qq * 4;
        cp16(bb + SEG_Z + so, g_zp + gr);
        cp16(bb + SEG_CB + so, g_cbp + gc);
        cp16(bb + SEG_C + so, g_ctxp + gr);
        cp16(bb + SEG_GW + so, g_gwp + gc);
        asm volatile("cp.async.commit_group;" ::: "memory");
    };

    float accd[2][4][4], accg[2][4][4];
#pragma unroll
    for (int mt = 0; mt < 2; mt++)
#pragma unroll
        for (int nt = 0; nt < 4; nt++)
#pragma unroll
            for (int e = 0; e < 4; e++) { accd[mt][nt][e] = 0.f; accg[mt][nt][e] = 0.f; }

    // fragment base addresses (per 8-row subgroup s: rows g+8s)
    uint32_t aZ[4], aB[4], aC[4], aG[4];
#pragma unroll
    for (int s = 0; s < 4; s++) {
        aZ[s] = SEG_Z  + (uint32_t)(warpM * 32 + g + 8 * s) * 64 + tig * 16;
        aB[s] = SEG_CB + (uint32_t)(warpN * 32 + g + 8 * s) * 64 + tig * 16;
        aC[s] = SEG_C  + (uint32_t)(warpM * 32 + g + 8 * s) * 64 + tig * 16;
        aG[s] = SEG_GW + (uint32_t)(warpN * 32 + g + 8 * s) * 64 + tig * 16;
    }

    // prologue: 2 stages in flight
    load_stage(0, 0);
    load_stage(1, 1);

    int buf = 0;
    for (int c = 0; c < NCHUNK; ++c) {
        if (c + 1 < NCHUNK) asm volatile("cp.async.wait_group 1;" ::: "memory");
        else                asm volatile("cp.async.wait_group 0;" ::: "memory");
        __syncthreads();
        if (c + 2 < NCHUNK) {
            int nb = buf + 2; if (nb >= NSTAGE) nb -= NSTAGE;
            load_stage(c + 2, nb);
        }
        const uint32_t bb = sbu + (uint32_t)buf * STAGE;

        // ---- dot GEMM (fp16): 2 k16-steps ----
        {
            uint32_t ax[4][4], bx[4][4];
#pragma unroll
            for (int s = 0; s < 4; s++) {
                uint4 vz = lds128(bb + aZ[s]);
                ax[s][0] = vz.x; ax[s][1] = vz.y; ax[s][2] = vz.z; ax[s][3] = vz.w;
                uint4 vb = lds128(bb + aB[s]);
                bx[s][0] = vb.x; bx[s][1] = vb.y; bx[s][2] = vb.z; bx[s][3] = vb.w;
            }
#pragma unroll
            for (int t = 0; t < 2; t++) {
                uint32_t af0[4] = {ax[0][2*t], ax[1][2*t], ax[0][2*t+1], ax[1][2*t+1]};
                uint32_t af1[4] = {ax[2][2*t], ax[3][2*t], ax[2][2*t+1], ax[3][2*t+1]};
#pragma unroll
                for (int nt = 0; nt < 4; nt++) {
                    uint32_t bf2[2] = {bx[nt][2*t], bx[nt][2*t+1]};
                    mma_f16(accd[0][nt], af0, bf2);
                    mma_f16(accd[1][nt], af1, bf2);
                }
            }
        }
        // ---- gate GEMM (bf16): 2 k16-steps ----
        {
            uint32_t ax[4][4], bx[4][4];
#pragma unroll
            for (int s = 0; s < 4; s++) {
                uint4 vc = lds128(bb + aC[s]);
                ax[s][0] = vc.x; ax[s][1] = vc.y; ax[s][2] = vc.z; ax[s][3] = vc.w;
                uint4 vw = lds128(bb + aG[s]);
                bx[s][0] = vw.x; bx[s][1] = vw.y; bx[s][2] = vw.z; bx[s][3] = vw.w;
            }
#pragma unroll
            for (int t = 0; t < 2; t++) {
                uint32_t af0[4] = {ax[0][2*t], ax[1][2*t], ax[0][2*t+1], ax[1][2*t+1]};
                uint32_t af1[4] = {ax[2][2*t], ax[3][2*t], ax[2][2*t+1], ax[3][2*t+1]};
#pragma unroll
                for (int nt = 0; nt < 4; nt++) {
                    uint32_t bf2[2] = {bx[nt][2*t], bx[nt][2*t+1]};
                    mma_bf16(accg[0][nt], af0, bf2);
                    mma_bf16(accg[1][nt], af1, bf2);
                }
            }
        }
        buf++; if (buf >= NSTAGE) buf = 0;
    }

    // ---- epilogue: bias + per-row top-2 ----
    float cnv[4][2], gbv[4][2];
#pragma unroll
    for (int nt = 0; nt < 4; nt++)
#pragma unroll
        for (int e = 0; e < 2; e++) {
            int col = cbase + warpN * 32 + nt * 8 + 2 * tig + e;
            cnv[nt][e] = g_cnorm[col];
            gbv[nt][e] = gate_b[col];
        }

    const float INF = __int_as_float(0x7f800000);
#pragma unroll
    for (int mt = 0; mt < 2; mt++)
#pragma unroll
        for (int hi = 0; hi < 2; hi++) {
            int rowg = rowBase + warpM * 32 + mt * 16 + hi * 8 + g;
            const float* adjr = adjacency + (size_t)prev_idx[rowg] * KSYM;
            float V1 = INF, V2 = INF;
            int   I1 = 0x7fffffff, I2 = 0x7fffffff;
#pragma unroll
            for (int nt = 0; nt < 4; nt++)
#pragma unroll
                for (int e = 0; e < 2; e++) {
                    int col = cbase + warpN * 32 + nt * 8 + 2 * tig + e;
                    float dot = accd[mt][nt][hi * 2 + e];
                    float gt  = accg[mt][nt][hi * 2 + e];
                    float adj = __ldg(adjr + col);
                    float sig = 1.f / (1.f + __expf(-adj));
                    float th  = tanh_approx(gt + gbv[nt][e]);
                    float s = fmaf(-2.f, dot, cnv[nt][e]) - 0.8f * sig * fmaf(0.5f, th, 1.f);
                    if (s < V1 || (s == V1 && col < I1)) { V2 = V1; I2 = I1; V1 = s; I1 = col; }
                    else if (s < V2 || (s == V2 && col < I2)) { V2 = s; I2 = col; }
                }
#pragma unroll
            for (int off = 1; off <= 2; off <<= 1) {
                float ov1 = __shfl_xor_sync(0xffffffffu, V1, off);
                int   oi1 = __shfl_xor_sync(0xffffffffu, I1, off);
                float ov2 = __shfl_xor_sync(0xffffffffu, V2, off);
                int   oi2 = __shfl_xor_sync(0xffffffffu, I2, off);
                if (ov1 < V1 || (ov1 == V1 && oi1 < I1)) {
                    float nv2; int ni2;
                    if (V1 < ov2 || (V1 == ov2 && I1 < oi2)) { nv2 = V1; ni2 = I1; }
                    else { nv2 = ov2; ni2 = oi2; }
                    V1 = ov1; I1 = oi1; V2 = nv2; I2 = ni2;
                } else if (ov1 < V2 || (ov1 == V2 && oi1 < I2)) {
                    V2 = ov1; I2 = oi1;
                }
            }
            if (tig == 0) {
                size_t o = ((size_t)rowg * RECORDS + blockIdx.x * 4 + warpN) * 2;
                g_top2v[o] = V1;  g_top2i[o] = I1;
                g_top2v[o + 1] = V2; g_top2i[o + 1] = I2;
            }
        }
}

// ---------------- 4. merge top-2s; fp64 refinement for near-ties ----------------
__global__ void merge_refine_kernel(const float* __restrict__ z_real,  const float* __restrict__ z_imag,
                                    const float* __restrict__ ctx_real, const float* __restrict__ ctx_imag,
                                    const int*   __restrict__ prev_idx,
                                    const float* __restrict__ codebook, const float* __restrict__ adjacency,
                                    const float* __restrict__ gate_w,   const float* __restrict__ gate_b,
                                    float* __restrict__ out) {
    int gwarp = (blockIdx.x * blockDim.x + threadIdx.x) >> 5;
    int lane = threadIdx.x & 31;
    if (gwarp >= N_ROWS) return;
    const int n = gwarp;
    const float INF = __int_as_float(0x7f800000);

    float v1 = INF, v2 = INF;
    int i1 = 0x7fffffff, i2 = 0x7fffffff;
    const size_t base = (size_t)n * (RECORDS * 2);
#pragma unroll
    for (int q = 0; q < 16; q++) {
        int e = lane + q * 32;
        float v = g_top2v[base + e];
        int ix  = g_top2i[base + e];
        if (v < v1 || (v == v1 && ix < i1)) { v2 = v1; i2 = i1; v1 = v; i1 = ix; }
        else if (v < v2 || (v == v2 && ix < i2)) { v2 = v; i2 = ix; }
    }
#pragma unroll
    for (int off = 16; off; off >>= 1) {
        float ov1 = __shfl_down_sync(0xffffffffu, v1, off);
        float ov2 = __shfl_down_sync(0xffffffffu, v2, off);
        int   oi1 = __shfl_down_sync(0xffffffffu, i1, off);
        int   oi2 = __shfl_down_sync(0xffffffffu, i2, off);
        if (ov1 < v1 || (ov1 == v1 && oi1 < i1)) { v2 = v1; i2 = i1; v1 = ov1; i1 = oi1; }
        else if (ov1 < v2 || (ov1 == v2 && oi1 < i2)) { v2 = ov1; i2 = oi1; }
        if (ov2 < v1 || (ov2 == v1 && oi2 < i1)) { v2 = v1; i2 = i1; v1 = ov2; i1 = oi2; }
        else if (ov2 < v2 || (ov2 == v2 && oi2 < i2)) { v2 = ov2; i2 = oi2; }
    }
    float bv1 = __shfl_sync(0xffffffffu, v1, 0);
    float bv2 = __shfl_sync(0xffffffffu, v2, 0);
    int   bi1 = __shfl_sync(0xffffffffu, i1, 0);
    int   bi2 = __shfl_sync(0xffffffffu, i2, 0);

    int pick = bi1;
    if (bv2 - bv1 < MARGIN) {
        double a0 = 0, a1 = 0, a2 = 0, a3 = 0, a4 = 0, a5 = 0;
        for (int t = lane; t < D2; t += 32) {
            double zt = (t < 512) ? (double)z_real[(size_t)n * 512 + t]
                                  : (double)z_imag[(size_t)n * 512 + t - 512];
            double xt = (t < 512) ? (double)ctx_real[(size_t)n * 512 + t]
                                  : (double)ctx_imag[(size_t)n * 512 + t - 512];
            double c1 = (double)codebook[(size_t)bi1 * D2 + t];
            double w1 = (double)gate_w[(size_t)bi1 * D2 + t];
            double c2 = (double)codebook[(size_t)bi2 * D2 + t];
            double w2 = (double)gate_w[(size_t)bi2 * D2 + t];
            a0 += c1 * c1; a1 += zt * c1; a2 += xt * w1;
            a3 += c2 * c2; a4 += zt * c2; a5 += xt * w2;
        }
        for (int o = 16; o; o >>= 1) {
            a0 += __shfl_down_sync(0xffffffffu, a0, o);
            a1 += __shfl_down_sync(0xffffffffu, a1, o);
            a2 += __shfl_down_sync(0xffffffffu, a2, o);
            a3 += __shfl_down_sync(0xffffffffu, a3, o);
            a4 += __shfl_down_sync(0xffffffffu, a4, o);
            a5 += __shfl_down_sync(0xffffffffu, a5, o);
        }
        if (lane == 0) {
            int p = prev_idx[n];
            double ad1 = (double)adjacency[(size_t)p * KSYM + bi1];
            double ad2 = (double)adjacency[(size_t)p * KSYM + bi2];
            double gb1 = (double)gate_b[bi1];
            double gb2 = (double)gate_b[bi2];
            double d1 = a0 - 2.0 * a1 - 0.8 * (1.0 / (1.0 + exp(-ad1))) * (1.0 + 0.5 * tanh(a2 + gb1));
            double d2 = a3 - 2.0 * a4 - 0.8 * (1.0 / (1.0 + exp(-ad2))) * (1.0 + 0.5 * tanh(a5 + gb2));
            pick = (d2 < d1 || (d2 == d1 && bi2 < bi1)) ? bi2 : bi1;
        }
        pick = __shfl_sync(0xffffffffu, pick, 0);
    }
    if (lane == 0) {
        g_midx[n] = pick;
        out[MIDX_OFF + n] = (float)pick;
        atomicAdd(&g_counts[pick], 1);
    }
}

// ---------------- 5. z_q gather, embed_sum scatter, loss ----------------
__global__ void scatter_kernel(const float* __restrict__ z_real, const float* __restrict__ z_imag,
                               const float* __restrict__ codebook, float* __restrict__ out) {
    const int n = blockIdx.x;
    const int m = g_midx[n];
    const int tid = threadIdx.x;
    const int d0 = tid * 4;

    float4 c = *(const float4*)(codebook + (size_t)m * D2 + d0);
    float4 z;
    if (d0 < 512) z = *(const float4*)(z_real + (size_t)n * 512 + d0);
    else          z = *(const float4*)(z_imag + (size_t)n * 512 + d0 - 512);

    *(float4*)(out + ZQ_OFF + (size_t)n * D2 + d0) = c;

    float* ea = out + NEA_OFF + (size_t)m * D2 + d0;
    atomicAdd(ea + 0, 0.01f * z.x);
    atomicAdd(ea + 1, 0.01f * z.y);
    atomicAdd(ea + 2, 0.01f * z.z);
    atomicAdd(ea + 3, 0.01f * z.w);

    float dx = c.x - z.x, dy = c.y - z.y, dz = c.z - z.z, dw = c.w - z.w;
    float lsum = dx * dx + dy * dy + dz * dz + dw * dw;

    __shared__ float sh[256];
    sh[tid] = lsum; __syncthreads();
    for (int o = 128; o > 0; o >>= 1) { if (tid < o) sh[tid] += sh[tid + o]; __syncthreads(); }
    if (tid == 0) atomicAdd(&g_loss, (double)sh[0]);
}

// ---------------- 6a. cluster-size EMA, cs, loss ----------------
__global__ void finalize_a_kernel(const float* __restrict__ cluster_size, float* __restrict__ out) {
    const int tid = threadIdx.x;  // 1024 threads
    float ncs[8];
    float psum = 0.f;
#pragma unroll
    for (int q = 0; q < 8; q++) {
        int k = tid * 8 + q;
        float v = cluster_size[k] * 0.99f + 0.01f * (float)g_counts[k];
        ncs[q] = v;
        out[NCS_OFF + k] = v;
        psum += v;
    }
    __shared__ float sh[1024];
    sh[tid] = psum; __syncthreads();
    for (int o = 512; o > 0; o >>= 1) { if (tid < o) sh[tid] += sh[tid + o]; __syncthreads(); }
    float ntot = sh[0];
#pragma unroll
    for (int q = 0; q < 8; q++) {
        float cs = (ncs[q] + 1e-6f) / (ntot + (float)KSYM * 1e-6f) * ntot;
        g_cs[tid * 8 + q] = cs;
    }
    if (tid == 0) out[LOSS_OFF] = (float)(1.25 * g_loss / 16777216.0);
}

// ---------------- 6b. new_codebook = new_embed_avg / cs ----------------
__global__ void finalize_b_kernel(float* __restrict__ out) {
    size_t total = (size_t)KSYM * D2;
    size_t stride = (size_t)gridDim.x * blockDim.x;
    for (size_t i = (size_t)blockIdx.x * blockDim.x + threadIdx.x; i < total; i += stride) {
        int k = (int)(i >> 10);
        out[NCB_OFF + i] = out[NEA_OFF + i] / g_cs[k];
    }
}

// ---------------- entry ----------------
extern "C" void kernel_launch(void* const* d_in, const int* in_sizes, int n_in,
                              void* d_out, int out_size) {
    const float* z_real     = (const float*)d_in[0];
    const float* z_imag     = (const float*)d_in[1];
    const float* ctx_real   = (const float*)d_in[2];
    const float* ctx_imag   = (const float*)d_in[3];
    const int*   prev_idx   = (const int*)d_in[4];
    const float* codebook   = (const float*)d_in[5];
    const float* adjacency  = (const float*)d_in[6];
    const float* gate_w     = (const float*)d_in[7];
    const float* gate_b     = (const float*)d_in[8];
    const float* cluster_sz = (const float*)d_in[9];
    const float* embed_avg  = (const float*)d_in[10];
    float* out = (float*)d_out;

    cudaFuncSetAttribute(score_mma_kernel, cudaFuncAttributeMaxDynamicSharedMemorySize, SMEM_BYTES);

    perm_z_kernel<<<4096, 256>>>(z_real, z_imag);
    perm_cb_kernel<<<4096, 256>>>(codebook);
    perm_ctx_kernel<<<4096, 256>>>(ctx_real, ctx_imag);
    perm_gw_kernel<<<4096, 256>>>(gate_w);
    prep_cnorm_kernel<<<KSYM, 256>>>(codebook);
    init_kernel<<<8192, 256>>>(embed_avg, out);
    // blockIdx.x = column tile (fast) so codebook/gate_w stay L2-resident
    score_mma_kernel<<<dim3(KSYM / BN, N_ROWS / BM), 512, SMEM_BYTES>>>(
        prev_idx, adjacency, gate_b);
    merge_refine_kernel<<<N_ROWS / 8, 256>>>(z_real, z_imag, ctx_real, ctx_imag,
                                             prev_idx, codebook, adjacency, gate_w, gate_b, out);
    scatter_kernel<<<N_ROWS, 256>>>(z_real, z_imag, codebook, out);
    finalize_a_kernel<<<1, 1024>>>(cluster_sz, out);
    finalize_b_kernel<<<8192, 256>>>(out);
}